// round 12
// baseline (speedup 1.0000x reference)
#include <cuda_runtime.h>
#include <cuda_bf16.h>
#include <cstdint>

// ---------------- problem constants ----------------
#define NB   256      // batch
#define TQ   64       // quantized time
#define HD   256      // hidden dim
#define KC   8192     // n_embeddings

// output packing: (out, codebook_loss, commitment_loss, indices)
#define OUT_ELEMS   (256*1024*32)      // 8388608
#define LOSS_OFF    OUT_ELEMS
#define IDX_OFF     (OUT_ELEMS + 2)

// encoder/proj transposed-weight offsets (in g_wt)
#define WT0  0
#define WT1  6144
#define WT2  30720
#define WTP  129024
#define WT_TOT 194560

// deconv duplicated-weight offsets (in g_wtd)
#define WD0  0
#define WD1  393216
#define WD2  589824
#define WD3  638976
#define WD_TOT 651264

typedef unsigned long long u64;

// ---------------- f32x2 helpers ----------------
__device__ __forceinline__ u64 ffma2(u64 a, u64 b, u64 c) {
    u64 d;
    asm("fma.rn.f32x2 %0, %1, %2, %3;" : "=l"(d) : "l"(a), "l"(b), "l"(c));
    return d;
}
__device__ __forceinline__ u64 pack2(float lo, float hi) {
    u64 d;
    asm("mov.b64 %0, {%1, %2};" : "=l"(d) : "f"(lo), "f"(hi));
    return d;
}
__device__ __forceinline__ float f2lo(u64 v) {
    float lo, hi; asm("mov.b64 {%0, %1}, %2;" : "=f"(lo), "=f"(hi) : "l"(v)); return lo;
}
__device__ __forceinline__ float f2hi(u64 v) {
    float lo, hi; asm("mov.b64 {%0, %1}, %2;" : "=f"(lo), "=f"(hi) : "l"(v)); return hi;
}
__device__ __forceinline__ void cp_async16(unsigned smem_addr, const void* gptr) {
    asm volatile("cp.async.cg.shared.global [%0], [%1], 16;" :: "r"(smem_addr), "l"(gptr));
}
__device__ __forceinline__ void cp_commit() { asm volatile("cp.async.commit_group;" ::: "memory"); }

// ---------------- mma.sync helpers (sm_80-era, valid on baseline sm_103) ----------
__device__ __forceinline__ uint32_t smem_to_u32(const void* smem_ptr) {
    uint32_t addr;
    asm("{ .reg .u64 tmp; cvta.to.shared.u64 tmp, %1; cvt.u32.u64 %0, tmp; }"
        : "=r"(addr) : "l"(smem_ptr));
    return addr;
}
__device__ __forceinline__ void ldsm4(uint32_t* r, uint32_t addr) {
    asm volatile("ldmatrix.sync.aligned.m8n8.x4.shared.b16 {%0,%1,%2,%3}, [%4];"
        : "=r"(r[0]), "=r"(r[1]), "=r"(r[2]), "=r"(r[3]) : "r"(addr));
}
__device__ __forceinline__ void mma_bf16(float* c, const uint32_t* a, const uint32_t* b) {
    asm volatile(
        "mma.sync.aligned.m16n8k16.row.col.f32.bf16.bf16.f32 "
        "{%0,%1,%2,%3}, {%4,%5,%6,%7}, {%8,%9}, {%0,%1,%2,%3};"
        : "+f"(c[0]), "+f"(c[1]), "+f"(c[2]), "+f"(c[3])
        : "r"(a[0]), "r"(a[1]), "r"(a[2]), "r"(a[3]), "r"(b[0]), "r"(b[1]));
}

// ---------------- device scratch ----------------
__device__ float g_h0[256*64*256];
__device__ float g_h1[256*128*128];
__device__ float g_h2[256*256*64];
__device__ float g_ze[256*256*64];
__device__ float g_zq[256*256*64];
__device__ float g_d0[256*256*128];
__device__ float g_d1[256*128*256];
__device__ float g_d2[256*64*512];
__device__ float g_wt[WT_TOT];
__device__ float g_wtd[WD_TOT];
__device__ __nv_bfloat16 g_eb0[8192*256];   // codebook bf16 [n][k]
__device__ float g_hn[KC];
__device__ int   g_idx[NB*TQ];
__device__ float g_loss[1];
__device__ int   g_flagcnt[1];
__device__ int   g_flagrows[16384];

// ---------------- combined weight transpose ----------------
struct WtArgs {
    const float* src[8];
    int dst_off[8];
    int cout[8];
    int cink[8];
    int start[8];
    int total;
};
__global__ void wtrans_all_kernel(WtArgs a, float* __restrict__ wt, float* __restrict__ wtd) {
    int i = blockIdx.x * 256 + threadIdx.x;
    if (i >= a.total) return;
    int s = 0;
    #pragma unroll
    for (int q = 1; q < 8; q++) if (i >= a.start[q]) s = q;
    int e  = i - a.start[s];
    int co = e / a.cink[s];
    int r  = e - co * a.cink[s];
    float v = a.src[s][e];
    if (s < 4) {
        wt[a.dst_off[s] + r * a.cout[s] + co] = v;
    } else {
        int o = a.dst_off[s] + (r * a.cout[s] + co) * 2;
        wtd[o] = v; wtd[o + 1] = v;
    }
}

// ---------------- codebook bf16 conversion (plain [n][k] layout) ----------------
__global__ void ebconv_kernel(const float* __restrict__ emb, __nv_bfloat16* __restrict__ e0) {
    int i = blockIdx.x * 256 + threadIdx.x;
    e0[i] = __float2bfloat16(emb[i]);
}

// ---------------- 0.5*||e||^2 (+ zero accumulators) ----------------
__global__ void enorm_kernel(const float* __restrict__ emb) {
    if (blockIdx.x == 0 && threadIdx.x == 0) { g_loss[0] = 0.f; g_flagcnt[0] = 0; }
    int n = blockIdx.x * 8 + (threadIdx.x >> 5);
    int lane = threadIdx.x & 31;
    const float* e = emb + (long)n * HD;
    float s = 0.f;
    #pragma unroll
    for (int c = lane; c < HD; c += 32) { float v = e[c]; s += v * v; }
    #pragma unroll
    for (int o = 16; o; o >>= 1) s += __shfl_xor_sync(0xffffffffu, s, o);
    if (lane == 0) g_hn[n] = 0.5f * s;
}

// ---------------- generic direct conv1d (k=3, strided; encoder) ----------------
template<int CIN, int COUT, int TT, int STRIDE, int PAD, bool RELU>
__global__ void conv1d_kernel(const float* __restrict__ in, const float* __restrict__ wt,
                              const float* __restrict__ bias, float* __restrict__ out,
                              int Tin, int Tout, int inB, int inC, int inT) {
    const int SW = STRIDE * (TT - 1) + 3;
    __shared__ float s_in[CIN][SW];
    int b   = blockIdx.x;
    int to0 = blockIdx.y * TT;
    int ti0 = STRIDE * to0 - PAD;

    for (int idx = threadIdx.x; idx < CIN * SW; idx += blockDim.x) {
        int ci = idx / SW, j = idx - ci * SW;
        int tg = ti0 + j;
        s_in[ci][j] = (tg >= 0 && tg < Tin)
            ? in[(long)b * inB + (long)ci * inC + (long)tg * inT] : 0.f;
    }
    __syncthreads();

    int co = threadIdx.x;
    float acc[TT];
    float bv = bias[co];
    #pragma unroll
    for (int t = 0; t < TT; t++) acc[t] = bv;

    for (int ci = 0; ci < CIN; ci++) {
        const float* sr = s_in[ci];
        float w0 = wt[(ci * 3 + 0) * COUT + co];
        float w1 = wt[(ci * 3 + 1) * COUT + co];
        float w2 = wt[(ci * 3 + 2) * COUT + co];
        #pragma unroll
        for (int t = 0; t < TT; t++) {
            acc[t] = fmaf(w0, sr[STRIDE * t + 0], acc[t]);
            acc[t] = fmaf(w1, sr[STRIDE * t + 1], acc[t]);
            acc[t] = fmaf(w2, sr[STRIDE * t + 2], acc[t]);
        }
    }
    long ob = (long)b * COUT * Tout + (long)co * Tout + to0;
    #pragma unroll
    for (int t = 0; t < TT; t++) {
        float v = acc[t];
        if (RELU) v = fmaxf(v, 0.f);
        out[ob + t] = v;
    }
}

// ---------------- 1x1 projection conv, f32x2 ----------------
__global__ void proj_kernel(const float* __restrict__ in, const float* __restrict__ wt,
                            const float* __restrict__ bias, float* __restrict__ out) {
    __shared__ float s_in[256][16];
    int b   = blockIdx.x;
    int to0 = blockIdx.y * 16;
    for (int idx = threadIdx.x; idx < 256 * 16; idx += 256) {
        int ci = idx >> 4, j = idx & 15;
        s_in[ci][j] = in[(long)b * (256 * 64) + ci * 64 + to0 + j];
    }
    __syncthreads();

    int co = threadIdx.x;
    float bv = bias[co];
    u64 acc[8];
    #pragma unroll
    for (int p = 0; p < 8; p++) acc[p] = pack2(bv, bv);

    for (int ci = 0; ci < 256; ci++) {
        float w = wt[ci * 256 + co];
        u64 ws = pack2(w, w);
        const u64* xr = (const u64*)&s_in[ci][0];
        #pragma unroll
        for (int p = 0; p < 8; p++) acc[p] = ffma2(ws, xr[p], acc[p]);
    }
    long ob = (long)b * (256 * 64) + (long)co * 64 + to0;
    #pragma unroll
    for (int p = 0; p < 8; p++) {
        out[ob + 2 * p + 0] = f2lo(acc[p]);
        out[ob + 2 * p + 1] = f2hi(acc[p]);
    }
}

// ---------------- deconv (ConvTranspose1d k=3 s=2 p=1 op=1), f32x2, dup weights ----
template<int CIN, int COUT, int TT, int G, bool RELU>
__global__ void deconv1d_kernel(const float* __restrict__ in, const float* __restrict__ wd_f,
                                const float* __restrict__ bias, float* __restrict__ out,
                                int Tin, long oB, long oCs, long oTs) {
    const int IW  = G * TT / 2 + 1;
    const int IWP = (IW | 1) + 1;
    const int IWL = IW + 1;
    __shared__ float s_in[CIN][IWP];
    __shared__ float s_sh[CIN][IWP];
    int b   = blockIdx.x;
    int to0 = blockIdx.y * (G * TT);
    int t0h = to0 >> 1;
    int nt  = blockDim.x * blockDim.y;
    int tid = threadIdx.y * blockDim.x + threadIdx.x;

    for (int idx = tid; idx < CIN * IWL; idx += nt) {
        int ci = idx / IWL, j = idx - ci * IWL;
        int tg = t0h + j;
        float v = (tg < Tin) ? in[(long)b * CIN * Tin + (long)ci * Tin + tg] : 0.f;
        if (j < IW) s_in[ci][j] = v;
        if (j > 0)  s_sh[ci][j - 1] = v;
    }
    __syncthreads();

    int co   = threadIdx.x;
    int base = threadIdx.y * TT;
    int H0   = base >> 1;
    float bv = bias[co];
    u64 aE[TT / 4], aO[TT / 4];
    #pragma unroll
    for (int p = 0; p < TT / 4; p++) { aE[p] = pack2(bv, bv); aO[p] = pack2(bv, bv); }

    const u64* wd = (const u64*)wd_f;
    for (int ci = 0; ci < CIN; ci++) {
        u64 w0 = wd[(ci * 3 + 0) * COUT + co];
        u64 w1 = wd[(ci * 3 + 1) * COUT + co];
        u64 w2 = wd[(ci * 3 + 2) * COUT + co];
        #pragma unroll
        for (int p = 0; p < 4; p++) {
            u64 X = *(const u64*)&s_in[ci][H0 + 2 * p];
            u64 Z = *(const u64*)&s_sh[ci][H0 + 2 * p];
            aE[p] = ffma2(w1, X, aE[p]);
            aO[p] = ffma2(w0, X, aO[p]);
            aO[p] = ffma2(w2, Z, aO[p]);
        }
    }
    long ob = (long)b * oB + (long)co * oCs;
    #pragma unroll
    for (int p = 0; p < 4; p++) {
        float v0 = f2lo(aE[p]), v1 = f2lo(aO[p]), v2 = f2hi(aE[p]), v3 = f2hi(aO[p]);
        if (RELU) { v0 = fmaxf(v0, 0.f); v1 = fmaxf(v1, 0.f); v2 = fmaxf(v2, 0.f); v3 = fmaxf(v3, 0.f); }
        long t = to0 + base + 4 * p;
        out[ob + (t + 0) * oTs] = v0;
        out[ob + (t + 1) * oTs] = v1;
        out[ob + (t + 2) * oTs] = v2;
        out[ob + (t + 3) * oTs] = v3;
    }
}

// ---------------- VQ: mma.sync bf16 SINGLE-pass GEMM + argmax + top-2 margin -------
// CTA = 256 thr (8 warps: 4 x m16, 2 x n32), one batch (64 rows). Grid = 256,
// 2 CTAs/SM -> single wave. Approx scores (rms err ~3e-3); rows with top-2 margin
// < 0.12 get exact fp32 rescore in vq_fallback_kernel.
#define VQ_A0   0
#define VQ_BOFF 32768
#define VQT_SMEM 98304
#define VQ_BST(stage) (VQ_BOFF + (stage) * 32768)

__device__ __forceinline__ void vq_fill_stage(uint32_t smem_base, int stage, int tile,
                                              const __nv_bfloat16* e0, int tid) {
    uint32_t b0 = smem_base + VQ_BST(stage);
    #pragma unroll
    for (int i = 0; i < 8; i++) {
        int c = tid + i * 256;             // 2048 chunks of 16B
        int row = c >> 5, cc = c & 31;
        uint32_t dst = (uint32_t)(row * 512) + (uint32_t)((cc ^ (row & 7)) << 4);
        long srcoff = ((long)tile * 64 + row) * 256 + cc * 8;
        cp_async16(b0 + dst, e0 + srcoff);
    }
}

__global__ __launch_bounds__(256, 2)
void vq_mma_kernel(const float* __restrict__ ze,
                   const __nv_bfloat16* __restrict__ e0,
                   const float* __restrict__ hn, int* __restrict__ out_idx,
                   int* __restrict__ flag_cnt, int* __restrict__ flag_rows) {
    extern __shared__ char smem[];
    uint32_t smem_base = smem_to_u32(smem);
    int tid = threadIdx.x;
    int cta = blockIdx.x;                   // batch index

    // prefetch B tile 0 (overlaps A conversion)
    vq_fill_stage(smem_base, 0, 0, e0, tid);
    cp_commit();

    // ---- A fill: z -> bf16, swizzled smem ----
    {
        int m = tid & 63, kseg = tid >> 6;  // 4 threads per row, 64 k each
        const float* zb = ze + (long)cta * (HD * TQ);
        for (int kk = 0; kk < 64; kk++) {
            int k = kseg * 64 + kk;
            float v = zb[k * 64 + m];       // coalesced across m
            uint32_t off = (uint32_t)(m * 512) + (uint32_t)((((k >> 3) ^ (m & 7)) << 4) + (k & 7) * 2);
            *(__nv_bfloat16*)(smem + VQ_A0 + off) = __float2bfloat16(v);
        }
    }
    asm volatile("cp.async.wait_group 0;" ::: "memory");
    __syncthreads();

    // ---- per-thread fragment address precompute (mapping validated in R11) ----
    int lane = tid & 31, wid = tid >> 5;
    int wm = wid & 3, wn = wid >> 2;
    int mrow = wm * 16 + (lane & 15);
    int khiA = lane >> 4;
    uint32_t aRow = (uint32_t)(mrow * 512);
    int r7A = mrow & 7;
    int nl   = (lane & 7) | ((lane >> 1) & 8);
    int khiB = (lane >> 3) & 1;
    int nrow0 = wn * 32 + nl;
    int nrow1 = nrow0 + 16;
    uint32_t bRow0 = (uint32_t)(nrow0 * 512);
    uint32_t bRow1 = (uint32_t)(nrow1 * 512);
    int r7B0 = nrow0 & 7, r7B1 = nrow1 & 7;

    float best0 = -3.4e38f, sec0 = -3.4e38f, best1 = -3.4e38f, sec1 = -3.4e38f;
    int   idx0 = 0, idx1 = 0;
    const float2* hn2 = (const float2*)hn;

    for (int tile = 0; tile < 128; tile++) {
        int stage = tile & 1;
        if (tile + 1 < 128) {
            vq_fill_stage(smem_base, stage ^ 1, tile + 1, e0, tid);
            cp_commit();
            asm volatile("cp.async.wait_group 1;" ::: "memory");
        } else {
            asm volatile("cp.async.wait_group 0;" ::: "memory");
        }
        __syncthreads();

        uint32_t sb0 = smem_base + VQ_BST(stage);

        float acc[4][4];
        #pragma unroll
        for (int j = 0; j < 4; j++)
            #pragma unroll
            for (int q = 0; q < 4; q++) acc[j][q] = 0.f;

        #pragma unroll
        for (int ks = 0; ks < 16; ks++) {
            uint32_t a0[4], b0[8];
            uint32_t offA = (uint32_t)(((2 * ks + khiA) ^ r7A) << 4);
            ldsm4(a0, smem_base + VQ_A0 + aRow + offA);
            uint32_t cB = (uint32_t)(2 * ks + khiB);
            ldsm4(b0 + 0, sb0 + ((cB ^ (uint32_t)r7B0) << 4) + bRow0);  // n 0-15
            ldsm4(b0 + 4, sb0 + ((cB ^ (uint32_t)r7B1) << 4) + bRow1);  // n 16-31
            mma_bf16(acc[0], a0, b0 + 0);
            mma_bf16(acc[1], a0, b0 + 2);
            mma_bf16(acc[2], a0, b0 + 4);
            mma_bf16(acc[3], a0, b0 + 6);
        }

        // epilogue: scores & top-2 update (ascending n within thread)
        int nb = tile * 64 + wn * 32 + (lane & 3) * 2;
        #pragma unroll
        for (int j = 0; j < 4; j++) {
            int n = nb + j * 8;
            float2 h = __ldg(&hn2[n >> 1]);
            float s0 = acc[j][0] - h.x, s1 = acc[j][1] - h.y;
            float s2 = acc[j][2] - h.x, s3 = acc[j][3] - h.y;
            if (s0 > best0) { sec0 = best0; best0 = s0; idx0 = n; }     else if (s0 > sec0) sec0 = s0;
            if (s1 > best0) { sec0 = best0; best0 = s1; idx0 = n + 1; } else if (s1 > sec0) sec0 = s1;
            if (s2 > best1) { sec1 = best1; best1 = s2; idx1 = n; }     else if (s2 > sec1) sec1 = s2;
            if (s3 > best1) { sec1 = best1; best1 = s3; idx1 = n + 1; } else if (s3 > sec1) sec1 = s3;
        }
        __syncthreads();
    }

    // ---- cross-lane merge within 4-lane row groups ----
    #pragma unroll
    for (int o = 1; o < 4; o <<= 1) {
        float ob = __shfl_xor_sync(0xffffffffu, best0, o);
        float os = __shfl_xor_sync(0xffffffffu, sec0, o);
        int   oi = __shfl_xor_sync(0xffffffffu, idx0, o);
        if (ob > best0)       { sec0 = fmaxf(best0, os); best0 = ob; idx0 = oi; }
        else if (ob == best0) { sec0 = best0; idx0 = min(idx0, oi); }
        else                  { sec0 = fmaxf(sec0, ob); }
        ob = __shfl_xor_sync(0xffffffffu, best1, o);
        os = __shfl_xor_sync(0xffffffffu, sec1, o);
        oi = __shfl_xor_sync(0xffffffffu, idx1, o);
        if (ob > best1)       { sec1 = fmaxf(best1, os); best1 = ob; idx1 = oi; }
        else if (ob == best1) { sec1 = best1; idx1 = min(idx1, oi); }
        else                  { sec1 = fmaxf(sec1, ob); }
    }

    // ---- cross-warp (wn) reduce via smem (A region is free now) ----
    float* rb = (float*)smem;            // [64][2]
    float* rs = rb + 128;                // [64][2]
    int*   ri = (int*)(rb + 256);        // [64][2]
    if ((lane & 3) == 0) {
        int r0 = wm * 16 + (lane >> 2);
        rb[r0 * 2 + wn] = best0; rs[r0 * 2 + wn] = sec0; ri[r0 * 2 + wn] = idx0;
        int r1 = r0 + 8;
        rb[r1 * 2 + wn] = best1; rs[r1 * 2 + wn] = sec1; ri[r1 * 2 + wn] = idx1;
    }
    __syncthreads();
    if (tid < 64) {
        float b = rb[tid * 2], s = rs[tid * 2];
        int   i = ri[tid * 2];
        float ob = rb[tid * 2 + 1], os = rs[tid * 2 + 1];
        int   oi = ri[tid * 2 + 1];
        if (ob > b)       { s = fmaxf(b, os); b = ob; i = oi; }
        else if (ob == b) { s = b; i = min(i, oi); }
        else              { s = fmaxf(s, ob); }
        int gr = cta * 64 + tid;
        out_idx[gr] = i;
        if (b - s < 0.12f) {
            int sl = atomicAdd(flag_cnt, 1);
            flag_rows[sl] = gr;
        }
    }
}

// ---------------- exact fp32 rescore of margin-flagged rows ----------------
__global__ void vq_fallback_kernel(const float* __restrict__ ze, const float* __restrict__ emb,
                                   const float* __restrict__ hn) {
    if ((int)blockIdx.x >= g_flagcnt[0]) return;
    __shared__ float zrow[256];
    __shared__ float rv[256];
    __shared__ int   ri[256];
    int r = g_flagrows[blockIdx.x];
    int b = r >> 6, t = r & 63;
    int k = threadIdx.x;
    zrow[k] = ze[(long)b * (HD * TQ) + k * TQ + t];
    __syncthreads();
    float best = -3.4e38f; int bidx = 0;
    for (int n = k; n < KC; n += 256) {
        const float* e = emb + (long)n * HD;
        float s = -hn[n];
        #pragma unroll 8
        for (int kk = 0; kk < HD; kk++) s = fmaf(zrow[kk], e[kk], s);
        if (s > best) { best = s; bidx = n; }
    }
    rv[k] = best; ri[k] = bidx;
    __syncthreads();
    if (k == 0) {
        float bv = rv[0]; int bi = ri[0];
        for (int j = 1; j < 256; j++)
            if (rv[j] > bv || (rv[j] == bv && ri[j] < bi)) { bv = rv[j]; bi = ri[j]; }
        g_idx[r] = bi;
    }
}

// ---------------- gather z_q + loss sum ----------------
__global__ void loss_gather_kernel(const float* __restrict__ ze, const float* __restrict__ emb) {
    int m = blockIdx.x;
    int b = m >> 6, t = m & 63;
    int c = threadIdx.x;
    int e = g_idx[m];
    float q = emb[(long)e * HD + c];
    long zoff = (long)b * (HD * TQ) + (long)c * TQ + t;
    float z = ze[zoff];
    g_zq[zoff] = q;
    float d = z - q;
    float s = d * d;
    #pragma unroll
    for (int o = 16; o; o >>= 1) s += __shfl_down_sync(0xffffffffu, s, o);
    __shared__ float ws[8];
    if ((c & 31) == 0) ws[c >> 5] = s;
    __syncthreads();
    if (c == 0) {
        float tot = 0.f;
        #pragma unroll
        for (int i = 0; i < 8; i++) tot += ws[i];
        atomicAdd(g_loss, tot);
    }
}

// ---------------- indices + losses to output ----------------
__global__ void idxout_kernel(float* out) {
    int m = blockIdx.x * 256 + threadIdx.x;
    out[IDX_OFF + m] = (float)g_idx[m];
    if (m == 0) {
        float l = g_loss[0] * (1.f / 4194304.f);
        out[LOSS_OFF + 0] = l;
        out[LOSS_OFF + 1] = l;
    }
}

// ---------------- launch ----------------
extern "C" void kernel_launch(void* const* d_in, const int* in_sizes, int n_in,
                              void* d_out, int out_size) {
    const float* x   = (const float*)d_in[0];
    const float* ew0 = (const float*)d_in[1];  const float* eb0b = (const float*)d_in[2];
    const float* ew1 = (const float*)d_in[3];  const float* eb1b = (const float*)d_in[4];
    const float* ew2 = (const float*)d_in[5];  const float* eb2b = (const float*)d_in[6];
    const float* pw  = (const float*)d_in[7];  const float* pb   = (const float*)d_in[8];
    const float* emb = (const float*)d_in[9];
    const float* dw0 = (const float*)d_in[10]; const float* db0 = (const float*)d_in[11];
    const float* dw1 = (const float*)d_in[12]; const float* db1 = (const float*)d_in[13];
    const float* dw2 = (const float*)d_in[14]; const float* db2 = (const float*)d_in[15];
    const float* dw3 = (const float*)d_in[16]; const float* db3 = (const float*)d_in[17];
    float* out = (float*)d_out;

    void* p;
    cudaGetSymbolAddress(&p, g_wt);   float* wt  = (float*)p;
    cudaGetSymbolAddress(&p, g_wtd);  float* wtd = (float*)p;
    cudaGetSymbolAddress(&p, g_eb0);  __nv_bfloat16* e0 = (__nv_bfloat16*)p;
    cudaGetSymbolAddress(&p, g_h0);   float* h0  = (float*)p;
    cudaGetSymbolAddress(&p, g_h1);   float* h1  = (float*)p;
    cudaGetSymbolAddress(&p, g_h2);   float* h2  = (float*)p;
    cudaGetSymbolAddress(&p, g_ze);   float* ze  = (float*)p;
    cudaGetSymbolAddress(&p, g_zq);   float* zq  = (float*)p;
    cudaGetSymbolAddress(&p, g_d0);   float* d0  = (float*)p;
    cudaGetSymbolAddress(&p, g_d1);   float* d1  = (float*)p;
    cudaGetSymbolAddress(&p, g_d2);   float* d2  = (float*)p;
    cudaGetSymbolAddress(&p, g_hn);   float* hn  = (float*)p;
    cudaGetSymbolAddress(&p, g_idx);  int*   ix  = (int*)p;
    cudaGetSymbolAddress(&p, g_flagcnt);  int* fcnt = (int*)p;
    cudaGetSymbolAddress(&p, g_flagrows); int* frow = (int*)p;

    cudaFuncSetAttribute(vq_mma_kernel, cudaFuncAttributeMaxDynamicSharedMemorySize, VQT_SMEM);

    // prep
    WtArgs wa;
    const float* srcs[8] = {ew0, ew1, ew2, pw, dw0, dw1, dw2, dw3};
    int offs[8]  = {WT0, WT1, WT2, WTP, WD0, WD1, WD2, WD3};
    int couts[8] = {64, 128, 256, 256, 256, 128, 64, 32};
    int cinks[8] = {32*3, 64*3, 128*3, 256, 256*3, 256*3, 128*3, 64*3};
    int acc = 0;
    for (int q = 0; q < 8; q++) {
        wa.src[q] = srcs[q]; wa.dst_off[q] = offs[q];
        wa.cout[q] = couts[q]; wa.cink[q] = cinks[q];
        wa.start[q] = acc; acc += couts[q] * cinks[q];
    }
    wa.total = acc;
    wtrans_all_kernel<<<(acc + 255) / 256, 256>>>(wa, wt, wtd);
    ebconv_kernel<<<(KC * HD) / 256, 256>>>(emb, e0);
    enorm_kernel<<<KC/8, 256>>>(emb);

    // encoder
    conv1d_kernel<32, 64, 16, 2, 1, true ><<<dim3(NB,16), 64 >>>(x,  wt+WT0, eb0b, h0, 512, 256, 512*32, 1,  32);
    conv1d_kernel<64, 128,16, 2, 1, true ><<<dim3(NB, 8), 128>>>(h0, wt+WT1, eb1b, h1, 256, 128, 64*256, 256, 1);
    conv1d_kernel<128,256,16, 2, 1, true ><<<dim3(NB, 4), 256>>>(h1, wt+WT2, eb2b, h2, 128, 64,  128*128,128, 1);
    proj_kernel<<<dim3(NB, 4), 256>>>(h2, wt+WTP, pb, ze);

    // vector quantizer (tensor core single-pass + exact fallback)
    vq_mma_kernel<<<NB, 256, VQT_SMEM>>>(ze, e0, hn, ix, fcnt, frow);
    vq_fallback_kernel<<<16384, 256>>>(ze, emb, hn);
    loss_gather_kernel<<<NB*TQ, 256>>>(ze, emb);

    // decoder
    deconv1d_kernel<256,256,16,1, true ><<<dim3(NB, 8), dim3(256,1)>>>(zq, wtd+WD0, db0, d0, 64,  256*128, 128, 1);
    deconv1d_kernel<256,128,16,1, true ><<<dim3(NB,16), dim3(128,1)>>>(d0, wtd+WD1, db1, d1, 128, 128*256, 256, 1);
    deconv1d_kernel<128,64, 16,2, true ><<<dim3(NB,16), dim3(64, 2)>>>(d1, wtd+WD2, db2, d2, 256, 64*512,  512, 1);
    deconv1d_kernel<64, 32, 16,4, false><<<dim3(NB,16), dim3(32, 4)>>>(d2, wtd+WD3, db3, out,512, 1024*32, 1,  32);

    // scalar outputs
    idxout_kernel<<<64, 256>>>(out);
}

// round 13
// speedup vs baseline: 6.3546x; 6.3546x over previous
#include <cuda_runtime.h>
#include <cuda_bf16.h>
#include <cstdint>

// ---------------- problem constants ----------------
#define NB   256      // batch
#define TQ   64       // quantized time
#define HD   256      // hidden dim
#define KC   8192     // n_embeddings

// output packing: (out, codebook_loss, commitment_loss, indices)
#define OUT_ELEMS   (256*1024*32)      // 8388608
#define LOSS_OFF    OUT_ELEMS
#define IDX_OFF     (OUT_ELEMS + 2)

// encoder/proj transposed-weight offsets (in g_wt)
#define WT0  0
#define WT1  6144
#define WT2  30720
#define WTP  129024
#define WT_TOT 194560

// deconv duplicated-weight offsets (in g_wtd)
#define WD0  0
#define WD1  393216
#define WD2  589824
#define WD3  638976
#define WD_TOT 651264

typedef unsigned long long u64;

// ---------------- f32x2 helpers ----------------
__device__ __forceinline__ u64 ffma2(u64 a, u64 b, u64 c) {
    u64 d;
    asm("fma.rn.f32x2 %0, %1, %2, %3;" : "=l"(d) : "l"(a), "l"(b), "l"(c));
    return d;
}
__device__ __forceinline__ u64 pack2(float lo, float hi) {
    u64 d;
    asm("mov.b64 %0, {%1, %2};" : "=l"(d) : "f"(lo), "f"(hi));
    return d;
}
__device__ __forceinline__ float f2lo(u64 v) {
    float lo, hi; asm("mov.b64 {%0, %1}, %2;" : "=f"(lo), "=f"(hi) : "l"(v)); return lo;
}
__device__ __forceinline__ float f2hi(u64 v) {
    float lo, hi; asm("mov.b64 {%0, %1}, %2;" : "=f"(lo), "=f"(hi) : "l"(v)); return hi;
}
__device__ __forceinline__ void cp_async16(unsigned smem_addr, const void* gptr) {
    asm volatile("cp.async.cg.shared.global [%0], [%1], 16;" :: "r"(smem_addr), "l"(gptr));
}
__device__ __forceinline__ void cp_commit() { asm volatile("cp.async.commit_group;" ::: "memory"); }

// ---------------- mma.sync helpers (sm_80-era, valid on baseline sm_103) ----------
__device__ __forceinline__ uint32_t smem_to_u32(const void* smem_ptr) {
    uint32_t addr;
    asm("{ .reg .u64 tmp; cvta.to.shared.u64 tmp, %1; cvt.u32.u64 %0, tmp; }"
        : "=r"(addr) : "l"(smem_ptr));
    return addr;
}
__device__ __forceinline__ void ldsm4(uint32_t* r, uint32_t addr) {
    asm volatile("ldmatrix.sync.aligned.m8n8.x4.shared.b16 {%0,%1,%2,%3}, [%4];"
        : "=r"(r[0]), "=r"(r[1]), "=r"(r[2]), "=r"(r[3]) : "r"(addr));
}
__device__ __forceinline__ void mma_bf16(float* c, const uint32_t* a, const uint32_t* b) {
    asm volatile(
        "mma.sync.aligned.m16n8k16.row.col.f32.bf16.bf16.f32 "
        "{%0,%1,%2,%3}, {%4,%5,%6,%7}, {%8,%9}, {%0,%1,%2,%3};"
        : "+f"(c[0]), "+f"(c[1]), "+f"(c[2]), "+f"(c[3])
        : "r"(a[0]), "r"(a[1]), "r"(a[2]), "r"(a[3]), "r"(b[0]), "r"(b[1]));
}

// ---------------- device scratch ----------------
__device__ float g_h0[256*64*256];
__device__ float g_h1[256*128*128];
__device__ float g_h2[256*256*64];
__device__ float g_ze[256*256*64];
__device__ float g_zq[256*256*64];
__device__ float g_d0[256*256*128];
__device__ float g_d1[256*128*256];
__device__ float g_d2[256*64*512];
__device__ float g_wt[WT_TOT];
__device__ float g_wtd[WD_TOT];
__device__ __nv_bfloat16 g_eb0[8192*256];   // codebook bf16 [n][k]
__device__ float g_hn[KC];
__device__ int   g_idx[NB*TQ];
__device__ float g_loss[1];
__device__ int   g_flagcnt[1];
__device__ int   g_flagrows[16384];

// ---------------- combined weight transpose ----------------
struct WtArgs {
    const float* src[8];
    int dst_off[8];
    int cout[8];
    int cink[8];
    int start[8];
    int total;
};
__global__ void wtrans_all_kernel(WtArgs a, float* __restrict__ wt, float* __restrict__ wtd) {
    int i = blockIdx.x * 256 + threadIdx.x;
    if (i >= a.total) return;
    int s = 0;
    #pragma unroll
    for (int q = 1; q < 8; q++) if (i >= a.start[q]) s = q;
    int e  = i - a.start[s];
    int co = e / a.cink[s];
    int r  = e - co * a.cink[s];
    float v = a.src[s][e];
    if (s < 4) {
        wt[a.dst_off[s] + r * a.cout[s] + co] = v;
    } else {
        int o = a.dst_off[s] + (r * a.cout[s] + co) * 2;
        wtd[o] = v; wtd[o + 1] = v;
    }
}

// ---------------- codebook bf16 conversion (plain [n][k] layout) ----------------
__global__ void ebconv_kernel(const float* __restrict__ emb, __nv_bfloat16* __restrict__ e0) {
    int i = blockIdx.x * 256 + threadIdx.x;
    e0[i] = __float2bfloat16(emb[i]);
}

// ---------------- 0.5*||e||^2 (+ zero accumulators) ----------------
__global__ void enorm_kernel(const float* __restrict__ emb) {
    if (blockIdx.x == 0 && threadIdx.x == 0) { g_loss[0] = 0.f; g_flagcnt[0] = 0; }
    int n = blockIdx.x * 8 + (threadIdx.x >> 5);
    int lane = threadIdx.x & 31;
    const float* e = emb + (long)n * HD;
    float s = 0.f;
    #pragma unroll
    for (int c = lane; c < HD; c += 32) { float v = e[c]; s += v * v; }
    #pragma unroll
    for (int o = 16; o; o >>= 1) s += __shfl_xor_sync(0xffffffffu, s, o);
    if (lane == 0) g_hn[n] = 0.5f * s;
}

// ---------------- generic direct conv1d (k=3, strided; encoder) ----------------
template<int CIN, int COUT, int TT, int STRIDE, int PAD, bool RELU>
__global__ void conv1d_kernel(const float* __restrict__ in, const float* __restrict__ wt,
                              const float* __restrict__ bias, float* __restrict__ out,
                              int Tin, int Tout, int inB, int inC, int inT) {
    const int SW = STRIDE * (TT - 1) + 3;
    __shared__ float s_in[CIN][SW];
    int b   = blockIdx.x;
    int to0 = blockIdx.y * TT;
    int ti0 = STRIDE * to0 - PAD;

    for (int idx = threadIdx.x; idx < CIN * SW; idx += blockDim.x) {
        int ci = idx / SW, j = idx - ci * SW;
        int tg = ti0 + j;
        s_in[ci][j] = (tg >= 0 && tg < Tin)
            ? in[(long)b * inB + (long)ci * inC + (long)tg * inT] : 0.f;
    }
    __syncthreads();

    int co = threadIdx.x;
    float acc[TT];
    float bv = bias[co];
    #pragma unroll
    for (int t = 0; t < TT; t++) acc[t] = bv;

    for (int ci = 0; ci < CIN; ci++) {
        const float* sr = s_in[ci];
        float w0 = wt[(ci * 3 + 0) * COUT + co];
        float w1 = wt[(ci * 3 + 1) * COUT + co];
        float w2 = wt[(ci * 3 + 2) * COUT + co];
        #pragma unroll
        for (int t = 0; t < TT; t++) {
            acc[t] = fmaf(w0, sr[STRIDE * t + 0], acc[t]);
            acc[t] = fmaf(w1, sr[STRIDE * t + 1], acc[t]);
            acc[t] = fmaf(w2, sr[STRIDE * t + 2], acc[t]);
        }
    }
    long ob = (long)b * COUT * Tout + (long)co * Tout + to0;
    #pragma unroll
    for (int t = 0; t < TT; t++) {
        float v = acc[t];
        if (RELU) v = fmaxf(v, 0.f);
        out[ob + t] = v;
    }
}

// ---------------- 1x1 projection conv, f32x2 ----------------
__global__ void proj_kernel(const float* __restrict__ in, const float* __restrict__ wt,
                            const float* __restrict__ bias, float* __restrict__ out) {
    __shared__ float s_in[256][16];
    int b   = blockIdx.x;
    int to0 = blockIdx.y * 16;
    for (int idx = threadIdx.x; idx < 256 * 16; idx += 256) {
        int ci = idx >> 4, j = idx & 15;
        s_in[ci][j] = in[(long)b * (256 * 64) + ci * 64 + to0 + j];
    }
    __syncthreads();

    int co = threadIdx.x;
    float bv = bias[co];
    u64 acc[8];
    #pragma unroll
    for (int p = 0; p < 8; p++) acc[p] = pack2(bv, bv);

    for (int ci = 0; ci < 256; ci++) {
        float w = wt[ci * 256 + co];
        u64 ws = pack2(w, w);
        const u64* xr = (const u64*)&s_in[ci][0];
        #pragma unroll
        for (int p = 0; p < 8; p++) acc[p] = ffma2(ws, xr[p], acc[p]);
    }
    long ob = (long)b * (256 * 64) + (long)co * 64 + to0;
    #pragma unroll
    for (int p = 0; p < 8; p++) {
        out[ob + 2 * p + 0] = f2lo(acc[p]);
        out[ob + 2 * p + 1] = f2hi(acc[p]);
    }
}

// ---------------- deconv (ConvTranspose1d k=3 s=2 p=1 op=1), f32x2, dup weights ----
template<int CIN, int COUT, int TT, int G, bool RELU>
__global__ void deconv1d_kernel(const float* __restrict__ in, const float* __restrict__ wd_f,
                                const float* __restrict__ bias, float* __restrict__ out,
                                int Tin, long oB, long oCs, long oTs) {
    const int IW  = G * TT / 2 + 1;
    const int IWP = (IW | 1) + 1;
    const int IWL = IW + 1;
    __shared__ float s_in[CIN][IWP];
    __shared__ float s_sh[CIN][IWP];
    int b   = blockIdx.x;
    int to0 = blockIdx.y * (G * TT);
    int t0h = to0 >> 1;
    int nt  = blockDim.x * blockDim.y;
    int tid = threadIdx.y * blockDim.x + threadIdx.x;

    for (int idx = tid; idx < CIN * IWL; idx += nt) {
        int ci = idx / IWL, j = idx - ci * IWL;
        int tg = t0h + j;
        float v = (tg < Tin) ? in[(long)b * CIN * Tin + (long)ci * Tin + tg] : 0.f;
        if (j < IW) s_in[ci][j] = v;
        if (j > 0)  s_sh[ci][j - 1] = v;
    }
    __syncthreads();

    int co   = threadIdx.x;
    int base = threadIdx.y * TT;
    int H0   = base >> 1;
    float bv = bias[co];
    u64 aE[TT / 4], aO[TT / 4];
    #pragma unroll
    for (int p = 0; p < TT / 4; p++) { aE[p] = pack2(bv, bv); aO[p] = pack2(bv, bv); }

    const u64* wd = (const u64*)wd_f;
    for (int ci = 0; ci < CIN; ci++) {
        u64 w0 = wd[(ci * 3 + 0) * COUT + co];
        u64 w1 = wd[(ci * 3 + 1) * COUT + co];
        u64 w2 = wd[(ci * 3 + 2) * COUT + co];
        #pragma unroll
        for (int p = 0; p < 4; p++) {
            u64 X = *(const u64*)&s_in[ci][H0 + 2 * p];
            u64 Z = *(const u64*)&s_sh[ci][H0 + 2 * p];
            aE[p] = ffma2(w1, X, aE[p]);
            aO[p] = ffma2(w0, X, aO[p]);
            aO[p] = ffma2(w2, Z, aO[p]);
        }
    }
    long ob = (long)b * oB + (long)co * oCs;
    #pragma unroll
    for (int p = 0; p < 4; p++) {
        float v0 = f2lo(aE[p]), v1 = f2lo(aO[p]), v2 = f2hi(aE[p]), v3 = f2hi(aO[p]);
        if (RELU) { v0 = fmaxf(v0, 0.f); v1 = fmaxf(v1, 0.f); v2 = fmaxf(v2, 0.f); v3 = fmaxf(v3, 0.f); }
        long t = to0 + base + 4 * p;
        out[ob + (t + 0) * oTs] = v0;
        out[ob + (t + 1) * oTs] = v1;
        out[ob + (t + 2) * oTs] = v2;
        out[ob + (t + 3) * oTs] = v3;
    }
}

// ---------------- VQ: mma.sync bf16 SINGLE-pass GEMM + argmax + top-2 margin -------
// CTA = 256 thr (8 warps: 4 x m16, 2 x n32), one batch (64 rows). Grid = 256,
// 2 CTAs/SM. Approx scores (max err ~0.016); rows with top-2 margin < 0.05 get
// exact fp32 rescore in the batched fallback.
#define VQ_A0   0
#define VQ_BOFF 32768
#define VQT_SMEM 98304
#define VQ_BST(stage) (VQ_BOFF + (stage) * 32768)
#define VQ_MARGIN 0.05f

__device__ __forceinline__ void vq_fill_stage(uint32_t smem_base, int stage, int tile,
                                              const __nv_bfloat16* e0, int tid) {
    uint32_t b0 = smem_base + VQ_BST(stage);
    #pragma unroll
    for (int i = 0; i < 8; i++) {
        int c = tid + i * 256;             // 2048 chunks of 16B
        int row = c >> 5, cc = c & 31;
        uint32_t dst = (uint32_t)(row * 512) + (uint32_t)((cc ^ (row & 7)) << 4);
        long srcoff = ((long)tile * 64 + row) * 256 + cc * 8;
        cp_async16(b0 + dst, e0 + srcoff);
    }
}

__global__ __launch_bounds__(256, 2)
void vq_mma_kernel(const float* __restrict__ ze,
                   const __nv_bfloat16* __restrict__ e0,
                   const float* __restrict__ hn, int* __restrict__ out_idx,
                   int* __restrict__ flag_cnt, int* __restrict__ flag_rows) {
    extern __shared__ char smem[];
    uint32_t smem_base = smem_to_u32(smem);
    int tid = threadIdx.x;
    int cta = blockIdx.x;                   // batch index

    // prefetch B tile 0 (overlaps A conversion)
    vq_fill_stage(smem_base, 0, 0, e0, tid);
    cp_commit();

    // ---- A fill: z -> bf16, swizzled smem ----
    {
        int m = tid & 63, kseg = tid >> 6;  // 4 threads per row, 64 k each
        const float* zb = ze + (long)cta * (HD * TQ);
        for (int kk = 0; kk < 64; kk++) {
            int k = kseg * 64 + kk;
            float v = zb[k * 64 + m];       // coalesced across m
            uint32_t off = (uint32_t)(m * 512) + (uint32_t)((((k >> 3) ^ (m & 7)) << 4) + (k & 7) * 2);
            *(__nv_bfloat16*)(smem + VQ_A0 + off) = __float2bfloat16(v);
        }
    }
    asm volatile("cp.async.wait_group 0;" ::: "memory");
    __syncthreads();

    // ---- per-thread fragment address precompute (mapping validated in R11) ----
    int lane = tid & 31, wid = tid >> 5;
    int wm = wid & 3, wn = wid >> 2;
    int mrow = wm * 16 + (lane & 15);
    int khiA = lane >> 4;
    uint32_t aRow = (uint32_t)(mrow * 512);
    int r7A = mrow & 7;
    int nl   = (lane & 7) | ((lane >> 1) & 8);
    int khiB = (lane >> 3) & 1;
    int nrow0 = wn * 32 + nl;
    int nrow1 = nrow0 + 16;
    uint32_t bRow0 = (uint32_t)(nrow0 * 512);
    uint32_t bRow1 = (uint32_t)(nrow1 * 512);
    int r7B0 = nrow0 & 7, r7B1 = nrow1 & 7;

    float best0 = -3.4e38f, sec0 = -3.4e38f, best1 = -3.4e38f, sec1 = -3.4e38f;
    int   idx0 = 0, idx1 = 0;
    const float2* hn2 = (const float2*)hn;

    for (int tile = 0; tile < 128; tile++) {
        int stage = tile & 1;
        if (tile + 1 < 128) {
            vq_fill_stage(smem_base, stage ^ 1, tile + 1, e0, tid);
            cp_commit();
            asm volatile("cp.async.wait_group 1;" ::: "memory");
        } else {
            asm volatile("cp.async.wait_group 0;" ::: "memory");
        }
        __syncthreads();

        uint32_t sb0 = smem_base + VQ_BST(stage);

        float acc[4][4];
        #pragma unroll
        for (int j = 0; j < 4; j++)
            #pragma unroll
            for (int q = 0; q < 4; q++) acc[j][q] = 0.f;

        #pragma unroll
        for (int ks = 0; ks < 16; ks++) {
            uint32_t a0[4], b0[8];
            uint32_t offA = (uint32_t)(((2 * ks + khiA) ^ r7A) << 4);
            ldsm4(a0, smem_base + VQ_A0 + aRow + offA);
            uint32_t cB = (uint32_t)(2 * ks + khiB);
            ldsm4(b0 + 0, sb0 + ((cB ^ (uint32_t)r7B0) << 4) + bRow0);  // n 0-15
            ldsm4(b0 + 4, sb0 + ((cB ^ (uint32_t)r7B1) << 4) + bRow1);  // n 16-31
            mma_bf16(acc[0], a0, b0 + 0);
            mma_bf16(acc[1], a0, b0 + 2);
            mma_bf16(acc[2], a0, b0 + 4);
            mma_bf16(acc[3], a0, b0 + 6);
        }

        // epilogue: scores & top-2 update (ascending n within thread)
        int nb = tile * 64 + wn * 32 + (lane & 3) * 2;
        #pragma unroll
        for (int j = 0; j < 4; j++) {
            int n = nb + j * 8;
            float2 h = __ldg(&hn2[n >> 1]);
            float s0 = acc[j][0] - h.x, s1 = acc[j][1] - h.y;
            float s2 = acc[j][2] - h.x, s3 = acc[j][3] - h.y;
            if (s0 > best0) { sec0 = best0; best0 = s0; idx0 = n; }     else if (s0 > sec0) sec0 = s0;
            if (s1 > best0) { sec0 = best0; best0 = s1; idx0 = n + 1; } else if (s1 > sec0) sec0 = s1;
            if (s2 > best1) { sec1 = best1; best1 = s2; idx1 = n; }     else if (s2 > sec1) sec1 = s2;
            if (s3 > best1) { sec1 = best1; best1 = s3; idx1 = n + 1; } else if (s3 > sec1) sec1 = s3;
        }
        __syncthreads();
    }

    // ---- cross-lane merge within 4-lane row groups ----
    #pragma unroll
    for (int o = 1; o < 4; o <<= 1) {
        float ob = __shfl_xor_sync(0xffffffffu, best0, o);
        float os = __shfl_xor_sync(0xffffffffu, sec0, o);
        int   oi = __shfl_xor_sync(0xffffffffu, idx0, o);
        if (ob > best0)       { sec0 = fmaxf(best0, os); best0 = ob; idx0 = oi; }
        else if (ob == best0) { sec0 = best0; idx0 = min(idx0, oi); }
        else                  { sec0 = fmaxf(sec0, ob); }
        ob = __shfl_xor_sync(0xffffffffu, best1, o);
        os = __shfl_xor_sync(0xffffffffu, sec1, o);
        oi = __shfl_xor_sync(0xffffffffu, idx1, o);
        if (ob > best1)       { sec1 = fmaxf(best1, os); best1 = ob; idx1 = oi; }
        else if (ob == best1) { sec1 = best1; idx1 = min(idx1, oi); }
        else                  { sec1 = fmaxf(sec1, ob); }
    }

    // ---- cross-warp (wn) reduce via smem (A region is free now) ----
    float* rb = (float*)smem;            // [64][2]
    float* rs = rb + 128;                // [64][2]
    int*   ri = (int*)(rb + 256);        // [64][2]
    if ((lane & 3) == 0) {
        int r0 = wm * 16 + (lane >> 2);
        rb[r0 * 2 + wn] = best0; rs[r0 * 2 + wn] = sec0; ri[r0 * 2 + wn] = idx0;
        int r1 = r0 + 8;
        rb[r1 * 2 + wn] = best1; rs[r1 * 2 + wn] = sec1; ri[r1 * 2 + wn] = idx1;
    }
    __syncthreads();
    if (tid < 64) {
        float b = rb[tid * 2], s = rs[tid * 2];
        int   i = ri[tid * 2];
        float ob = rb[tid * 2 + 1], os = rs[tid * 2 + 1];
        int   oi = ri[tid * 2 + 1];
        if (ob > b)       { s = fmaxf(b, os); b = ob; i = oi; }
        else if (ob == b) { s = b; i = min(i, oi); }
        else              { s = fmaxf(s, ob); }
        int gr = cta * 64 + tid;
        out_idx[gr] = i;
        if (b - s < VQ_MARGIN) {
            int sl = atomicAdd(flag_cnt, 1);
            flag_rows[sl] = gr;
        }
    }
}

// ---------------- batched exact fp32 rescore: 8 flagged rows per block ----------------
#define FB_ROWS 8
__global__ __launch_bounds__(256)
void vq_fallback_kernel(const float* __restrict__ ze, const float* __restrict__ emb,
                        const float* __restrict__ hn) {
    int base = blockIdx.x * FB_ROWS;
    int cnt = g_flagcnt[0];
    if (base >= cnt) return;
    __shared__ float zs[256][FB_ROWS];      // [k][row] 8KB
    __shared__ int   rowids[FB_ROWS];
    __shared__ float rv[256];
    __shared__ int   rix[256];
    int tid = threadIdx.x;
    int nrows = min(FB_ROWS, cnt - base);
    if (tid < FB_ROWS)
        rowids[tid] = g_flagrows[base + ((tid < nrows) ? tid : 0)];
    __syncthreads();
    #pragma unroll
    for (int j = 0; j < FB_ROWS; j++) {
        int r = rowids[j];
        int b = r >> 6, t = r & 63;
        zs[tid][j] = ze[(long)b * (HD * TQ) + tid * TQ + t];
    }
    __syncthreads();

    float best[FB_ROWS]; int bidx[FB_ROWS];
    #pragma unroll
    for (int j = 0; j < FB_ROWS; j++) { best[j] = -3.4e38f; bidx[j] = 0; }

    for (int i = 0; i < KC / 256; i++) {
        int n = tid + 256 * i;              // ascending per thread
        const float4* e4 = (const float4*)(emb + (long)n * HD);
        float acc[FB_ROWS];
        #pragma unroll
        for (int j = 0; j < FB_ROWS; j++) acc[j] = 0.f;
        #pragma unroll 4
        for (int k4 = 0; k4 < 64; k4++) {
            float4 ev = e4[k4];
            #pragma unroll
            for (int j = 0; j < FB_ROWS; j++) {
                acc[j] = fmaf(ev.x, zs[4 * k4 + 0][j], acc[j]);
                acc[j] = fmaf(ev.y, zs[4 * k4 + 1][j], acc[j]);
                acc[j] = fmaf(ev.z, zs[4 * k4 + 2][j], acc[j]);
                acc[j] = fmaf(ev.w, zs[4 * k4 + 3][j], acc[j]);
            }
        }
        float h = hn[n];
        #pragma unroll
        for (int j = 0; j < FB_ROWS; j++) {
            float s = acc[j] - h;
            if (s > best[j]) { best[j] = s; bidx[j] = n; }
        }
    }

    // per-row block reduction (lowest index wins ties)
    for (int j = 0; j < FB_ROWS; j++) {
        rv[tid] = best[j]; rix[tid] = bidx[j];
        __syncthreads();
        for (int o = 128; o > 0; o >>= 1) {
            if (tid < o) {
                float v2 = rv[tid + o]; int i2 = rix[tid + o];
                if (v2 > rv[tid] || (v2 == rv[tid] && i2 < rix[tid])) { rv[tid] = v2; rix[tid] = i2; }
            }
            __syncthreads();
        }
        if (tid == 0 && j < nrows) g_idx[rowids[j]] = rix[0];
        __syncthreads();
    }
}

// ---------------- gather z_q + loss sum ----------------
__global__ void loss_gather_kernel(const float* __restrict__ ze, const float* __restrict__ emb) {
    int m = blockIdx.x;
    int b = m >> 6, t = m & 63;
    int c = threadIdx.x;
    int e = g_idx[m];
    float q = emb[(long)e * HD + c];
    long zoff = (long)b * (HD * TQ) + (long)c * TQ + t;
    float z = ze[zoff];
    g_zq[zoff] = q;
    float d = z - q;
    float s = d * d;
    #pragma unroll
    for (int o = 16; o; o >>= 1) s += __shfl_down_sync(0xffffffffu, s, o);
    __shared__ float ws[8];
    if ((c & 31) == 0) ws[c >> 5] = s;
    __syncthreads();
    if (c == 0) {
        float tot = 0.f;
        #pragma unroll
        for (int i = 0; i < 8; i++) tot += ws[i];
        atomicAdd(g_loss, tot);
    }
}

// ---------------- indices + losses to output ----------------
__global__ void idxout_kernel(float* out) {
    int m = blockIdx.x * 256 + threadIdx.x;
    out[IDX_OFF + m] = (float)g_idx[m];
    if (m == 0) {
        float l = g_loss[0] * (1.f / 4194304.f);
        out[LOSS_OFF + 0] = l;
        out[LOSS_OFF + 1] = l;
    }
}

// ---------------- launch ----------------
extern "C" void kernel_launch(void* const* d_in, const int* in_sizes, int n_in,
                              void* d_out, int out_size) {
    const float* x   = (const float*)d_in[0];
    const float* ew0 = (const float*)d_in[1];  const float* eb0b = (const float*)d_in[2];
    const float* ew1 = (const float*)d_in[3];  const float* eb1b = (const float*)d_in[4];
    const float* ew2 = (const float*)d_in[5];  const float* eb2b = (const float*)d_in[6];
    const float* pw  = (const float*)d_in[7];  const float* pb   = (const float*)d_in[8];
    const float* emb = (const float*)d_in[9];
    const float* dw0 = (const float*)d_in[10]; const float* db0 = (const float*)d_in[11];
    const float* dw1 = (const float*)d_in[12]; const float* db1 = (const float*)d_in[13];
    const float* dw2 = (const float*)d_in[14]; const float* db2 = (const float*)d_in[15];
    const float* dw3 = (const float*)d_in[16]; const float* db3 = (const float*)d_in[17];
    float* out = (float*)d_out;

    void* p;
    cudaGetSymbolAddress(&p, g_wt);   float* wt  = (float*)p;
    cudaGetSymbolAddress(&p, g_wtd);  float* wtd = (float*)p;
    cudaGetSymbolAddress(&p, g_eb0);  __nv_bfloat16* e0 = (__nv_bfloat16*)p;
    cudaGetSymbolAddress(&p, g_h0);   float* h0  = (float*)p;
    cudaGetSymbolAddress(&p, g_h1);   float* h1  = (float*)p;
    cudaGetSymbolAddress(&p, g_h2);   float* h2  = (float*)p;
    cudaGetSymbolAddress(&p, g_ze);   float* ze  = (float*)p;
    cudaGetSymbolAddress(&p, g_zq);   float* zq  = (float*)p;
    cudaGetSymbolAddress(&p, g_d0);   float* d0  = (float*)p;
    cudaGetSymbolAddress(&p, g_d1);   float* d1  = (float*)p;
    cudaGetSymbolAddress(&p, g_d2);   float* d2  = (float*)p;
    cudaGetSymbolAddress(&p, g_hn);   float* hn  = (float*)p;
    cudaGetSymbolAddress(&p, g_idx);  int*   ix  = (int*)p;
    cudaGetSymbolAddress(&p, g_flagcnt);  int* fcnt = (int*)p;
    cudaGetSymbolAddress(&p, g_flagrows); int* frow = (int*)p;

    cudaFuncSetAttribute(vq_mma_kernel, cudaFuncAttributeMaxDynamicSharedMemorySize, VQT_SMEM);

    // prep
    WtArgs wa;
    const float* srcs[8] = {ew0, ew1, ew2, pw, dw0, dw1, dw2, dw3};
    int offs[8]  = {WT0, WT1, WT2, WTP, WD0, WD1, WD2, WD3};
    int couts[8] = {64, 128, 256, 256, 256, 128, 64, 32};
    int cinks[8] = {32*3, 64*3, 128*3, 256, 256*3, 256*3, 128*3, 64*3};
    int acc = 0;
    for (int q = 0; q < 8; q++) {
        wa.src[q] = srcs[q]; wa.dst_off[q] = offs[q];
        wa.cout[q] = couts[q]; wa.cink[q] = cinks[q];
        wa.start[q] = acc; acc += couts[q] * cinks[q];
    }
    wa.total = acc;
    wtrans_all_kernel<<<(acc + 255) / 256, 256>>>(wa, wt, wtd);
    ebconv_kernel<<<(KC * HD) / 256, 256>>>(emb, e0);
    enorm_kernel<<<KC/8, 256>>>(emb);

    // encoder
    conv1d_kernel<32, 64, 16, 2, 1, true ><<<dim3(NB,16), 64 >>>(x,  wt+WT0, eb0b, h0, 512, 256, 512*32, 1,  32);
    conv1d_kernel<64, 128,16, 2, 1, true ><<<dim3(NB, 8), 128>>>(h0, wt+WT1, eb1b, h1, 256, 128, 64*256, 256, 1);
    conv1d_kernel<128,256,16, 2, 1, true ><<<dim3(NB, 4), 256>>>(h1, wt+WT2, eb2b, h2, 128, 64,  128*128,128, 1);
    proj_kernel<<<dim3(NB, 4), 256>>>(h2, wt+WTP, pb, ze);

    // vector quantizer (tensor core single-pass + batched exact fallback)
    vq_mma_kernel<<<NB, 256, VQT_SMEM>>>(ze, e0, hn, ix, fcnt, frow);
    vq_fallback_kernel<<<16384 / FB_ROWS, 256>>>(ze, emb, hn);
    loss_gather_kernel<<<NB*TQ, 256>>>(ze, emb);

    // decoder
    deconv1d_kernel<256,256,16,1, true ><<<dim3(NB, 8), dim3(256,1)>>>(zq, wtd+WD0, db0, d0, 64,  256*128, 128, 1);
    deconv1d_kernel<256,128,16,1, true ><<<dim3(NB,16), dim3(128,1)>>>(d0, wtd+WD1, db1, d1, 128, 128*256, 256, 1);
    deconv1d_kernel<128,64, 16,2, true ><<<dim3(NB,16), dim3(64, 2)>>>(d1, wtd+WD2, db2, d2, 256, 64*512,  512, 1);
    deconv1d_kernel<64, 32, 16,4, false><<<dim3(NB,16), dim3(32, 4)>>>(d2, wtd+WD3, db3, out,512, 1024*32, 1,  32);

    // scalar outputs
    idxout_kernel<<<64, 256>>>(out);
}

// round 14
// speedup vs baseline: 6.5983x; 1.0383x over previous
#include <cuda_runtime.h>
#include <cuda_bf16.h>
#include <cstdint>

// ---------------- problem constants ----------------
#define NB   256      // batch
#define TQ   64       // quantized time
#define HD   256      // hidden dim
#define KC   8192     // n_embeddings

// output packing: (out, codebook_loss, commitment_loss, indices)
#define OUT_ELEMS   (256*1024*32)      // 8388608
#define LOSS_OFF    OUT_ELEMS
#define IDX_OFF     (OUT_ELEMS + 2)

// encoder/proj transposed-weight offsets (in g_wt)
#define WT0  0
#define WT1  6144
#define WT2  30720
#define WTP  129024
#define WT_TOT 194560

// deconv duplicated-weight offsets (in g_wtd)
#define WD0  0
#define WD1  393216
#define WD2  589824
#define WD3  638976
#define WD_TOT 651264

typedef unsigned long long u64;

// ---------------- f32x2 helpers ----------------
__device__ __forceinline__ u64 ffma2(u64 a, u64 b, u64 c) {
    u64 d;
    asm("fma.rn.f32x2 %0, %1, %2, %3;" : "=l"(d) : "l"(a), "l"(b), "l"(c));
    return d;
}
__device__ __forceinline__ u64 pack2(float lo, float hi) {
    u64 d;
    asm("mov.b64 %0, {%1, %2};" : "=l"(d) : "f"(lo), "f"(hi));
    return d;
}
__device__ __forceinline__ float f2lo(u64 v) {
    float lo, hi; asm("mov.b64 {%0, %1}, %2;" : "=f"(lo), "=f"(hi) : "l"(v)); return lo;
}
__device__ __forceinline__ float f2hi(u64 v) {
    float lo, hi; asm("mov.b64 {%0, %1}, %2;" : "=f"(lo), "=f"(hi) : "l"(v)); return hi;
}
__device__ __forceinline__ void cp_async16(unsigned smem_addr, const void* gptr) {
    asm volatile("cp.async.cg.shared.global [%0], [%1], 16;" :: "r"(smem_addr), "l"(gptr));
}
__device__ __forceinline__ void cp_commit() { asm volatile("cp.async.commit_group;" ::: "memory"); }

// ---------------- mma.sync helpers (sm_80-era, valid on baseline sm_103) ----------
__device__ __forceinline__ uint32_t smem_to_u32(const void* smem_ptr) {
    uint32_t addr;
    asm("{ .reg .u64 tmp; cvta.to.shared.u64 tmp, %1; cvt.u32.u64 %0, tmp; }"
        : "=r"(addr) : "l"(smem_ptr));
    return addr;
}
__device__ __forceinline__ void ldsm4(uint32_t* r, uint32_t addr) {
    asm volatile("ldmatrix.sync.aligned.m8n8.x4.shared.b16 {%0,%1,%2,%3}, [%4];"
        : "=r"(r[0]), "=r"(r[1]), "=r"(r[2]), "=r"(r[3]) : "r"(addr));
}
__device__ __forceinline__ void mma_bf16(float* c, const uint32_t* a, const uint32_t* b) {
    asm volatile(
        "mma.sync.aligned.m16n8k16.row.col.f32.bf16.bf16.f32 "
        "{%0,%1,%2,%3}, {%4,%5,%6,%7}, {%8,%9}, {%0,%1,%2,%3};"
        : "+f"(c[0]), "+f"(c[1]), "+f"(c[2]), "+f"(c[3])
        : "r"(a[0]), "r"(a[1]), "r"(a[2]), "r"(a[3]), "r"(b[0]), "r"(b[1]));
}

// ---------------- device scratch ----------------
__device__ float g_h0[256*64*256];
__device__ float g_h1[256*128*128];
__device__ float g_h2[256*256*64];
__device__ float g_ze[256*256*64];
__device__ float g_d0[256*256*128];
__device__ float g_d1[256*128*256];
__device__ float g_d2[256*64*512];
__device__ float g_wt[WT_TOT];
__device__ float g_wtd[WD_TOT];
__device__ __nv_bfloat16 g_eb0[8192*256];   // codebook bf16 [n][k]
__device__ float g_hn[KC];
__device__ int   g_idx[NB*TQ];
__device__ float g_score[NB*TQ];            // best score per row (exact after fallback)
__device__ float g_zn[NB*TQ];               // ||z_row||^2
__device__ int   g_flagcnt[1];
__device__ int   g_flagrows[16384];

// ---------------- combined weight transpose ----------------
struct WtArgs {
    const float* src[8];
    int dst_off[8];
    int cout[8];
    int cink[8];
    int start[8];
    int total;
};
__global__ void wtrans_all_kernel(WtArgs a, float* __restrict__ wt, float* __restrict__ wtd) {
    int i = blockIdx.x * 256 + threadIdx.x;
    if (i >= a.total) return;
    int s = 0;
    #pragma unroll
    for (int q = 1; q < 8; q++) if (i >= a.start[q]) s = q;
    int e  = i - a.start[s];
    int co = e / a.cink[s];
    int r  = e - co * a.cink[s];
    float v = a.src[s][e];
    if (s < 4) {
        wt[a.dst_off[s] + r * a.cout[s] + co] = v;
    } else {
        int o = a.dst_off[s] + (r * a.cout[s] + co) * 2;
        wtd[o] = v; wtd[o + 1] = v;
    }
}

// ---------------- codebook: 0.5*||e||^2 + bf16 convert (one pass) ----------------
__global__ void ebnorm_kernel(const float* __restrict__ emb, __nv_bfloat16* __restrict__ e0) {
    if (blockIdx.x == 0 && threadIdx.x == 0) g_flagcnt[0] = 0;
    int n = blockIdx.x * 8 + (threadIdx.x >> 5);
    int lane = threadIdx.x & 31;
    const float* e = emb + (long)n * HD;
    __nv_bfloat16* eo = e0 + (long)n * HD;
    float s = 0.f;
    #pragma unroll
    for (int c = lane; c < HD; c += 32) {
        float v = e[c];
        s += v * v;
        eo[c] = __float2bfloat16(v);
    }
    #pragma unroll
    for (int o = 16; o; o >>= 1) s += __shfl_xor_sync(0xffffffffu, s, o);
    if (lane == 0) g_hn[n] = 0.5f * s;
}

// ---------------- generic direct conv1d (k=3, strided; encoder) ----------------
// CFIRST: fill with ci-fastest thread mapping (for channel-contiguous inputs).
template<int CIN, int COUT, int TT, int STRIDE, int PAD, bool RELU, bool CFIRST>
__global__ void conv1d_kernel(const float* __restrict__ in, const float* __restrict__ wt,
                              const float* __restrict__ bias, float* __restrict__ out,
                              int Tin, int Tout, int inB, int inC, int inT) {
    const int SW = STRIDE * (TT - 1) + 3;
    __shared__ float s_in[CIN][SW];
    int b   = blockIdx.x;
    int to0 = blockIdx.y * TT;
    int ti0 = STRIDE * to0 - PAD;

    for (int idx = threadIdx.x; idx < CIN * SW; idx += blockDim.x) {
        int ci, j;
        if (CFIRST) { ci = idx % CIN; j = idx / CIN; }
        else        { ci = idx / SW;  j = idx - ci * SW; }
        int tg = ti0 + j;
        s_in[ci][j] = (tg >= 0 && tg < Tin)
            ? in[(long)b * inB + (long)ci * inC + (long)tg * inT] : 0.f;
    }
    __syncthreads();

    int co = threadIdx.x;
    float acc[TT];
    float bv = bias[co];
    #pragma unroll
    for (int t = 0; t < TT; t++) acc[t] = bv;

    for (int ci = 0; ci < CIN; ci++) {
        const float* sr = s_in[ci];
        float w0 = wt[(ci * 3 + 0) * COUT + co];
        float w1 = wt[(ci * 3 + 1) * COUT + co];
        float w2 = wt[(ci * 3 + 2) * COUT + co];
        #pragma unroll
        for (int t = 0; t < TT; t++) {
            acc[t] = fmaf(w0, sr[STRIDE * t + 0], acc[t]);
            acc[t] = fmaf(w1, sr[STRIDE * t + 1], acc[t]);
            acc[t] = fmaf(w2, sr[STRIDE * t + 2], acc[t]);
        }
    }
    long ob = (long)b * COUT * Tout + (long)co * Tout + to0;
    #pragma unroll
    for (int t = 0; t < TT; t++) {
        float v = acc[t];
        if (RELU) v = fmaxf(v, 0.f);
        out[ob + t] = v;
    }
}

// ---------------- 1x1 projection conv, f32x2 ----------------
__global__ void proj_kernel(const float* __restrict__ in, const float* __restrict__ wt,
                            const float* __restrict__ bias, float* __restrict__ out) {
    __shared__ float s_in[256][16];
    int b   = blockIdx.x;
    int to0 = blockIdx.y * 16;
    for (int idx = threadIdx.x; idx < 256 * 16; idx += 256) {
        int ci = idx >> 4, j = idx & 15;
        s_in[ci][j] = in[(long)b * (256 * 64) + ci * 64 + to0 + j];
    }
    __syncthreads();

    int co = threadIdx.x;
    float bv = bias[co];
    u64 acc[8];
    #pragma unroll
    for (int p = 0; p < 8; p++) acc[p] = pack2(bv, bv);

    for (int ci = 0; ci < 256; ci++) {
        float w = wt[ci * 256 + co];
        u64 ws = pack2(w, w);
        const u64* xr = (const u64*)&s_in[ci][0];
        #pragma unroll
        for (int p = 0; p < 8; p++) acc[p] = ffma2(ws, xr[p], acc[p]);
    }
    long ob = (long)b * (256 * 64) + (long)co * 64 + to0;
    #pragma unroll
    for (int p = 0; p < 8; p++) {
        out[ob + 2 * p + 0] = f2lo(acc[p]);
        out[ob + 2 * p + 1] = f2hi(acc[p]);
    }
}

// ---------------- deconv (ConvTranspose1d k=3 s=2 p=1 op=1), f32x2, dup weights ----
// GATHER: input rows come from emb[gidx[b*Tin + t]][ci] (z_q gather) instead of `in`.
template<int CIN, int COUT, int TT, int G, bool RELU, bool GATHER>
__global__ void deconv1d_kernel(const float* __restrict__ in, const float* __restrict__ wd_f,
                                const float* __restrict__ bias, float* __restrict__ out,
                                int Tin, long oB, long oCs, long oTs,
                                const int* __restrict__ gidx, const float* __restrict__ emb) {
    const int IW  = G * TT / 2 + 1;
    const int IWP = (IW | 1) + 1;
    const int IWL = IW + 1;
    __shared__ float s_in[CIN][IWP];
    __shared__ float s_sh[CIN][IWP];
    __shared__ int   s_e[IWL];
    int b   = blockIdx.x;
    int to0 = blockIdx.y * (G * TT);
    int t0h = to0 >> 1;
    int nt  = blockDim.x * blockDim.y;
    int tid = threadIdx.y * blockDim.x + threadIdx.x;

    if (GATHER) {
        if (tid < IWL) {
            int tg = t0h + tid;
            s_e[tid] = (tg < Tin) ? gidx[b * Tin + tg] : 0;
        }
        __syncthreads();
        // j-outer mapping: consecutive threads -> consecutive ci (coalesced emb row reads)
        for (int idx = tid; idx < CIN * IWL; idx += nt) {
            int ci = idx % CIN, j = idx / CIN;
            int tg = t0h + j;
            float v = (tg < Tin) ? emb[(long)s_e[j] * HD + ci] : 0.f;
            if (j < IW) s_in[ci][j] = v;
            if (j > 0)  s_sh[ci][j - 1] = v;
        }
    } else {
        for (int idx = tid; idx < CIN * IWL; idx += nt) {
            int ci = idx / IWL, j = idx - ci * IWL;
            int tg = t0h + j;
            float v = (tg < Tin) ? in[(long)b * CIN * Tin + (long)ci * Tin + tg] : 0.f;
            if (j < IW) s_in[ci][j] = v;
            if (j > 0)  s_sh[ci][j - 1] = v;
        }
    }
    __syncthreads();

    int co   = threadIdx.x;
    int base = threadIdx.y * TT;
    int H0   = base >> 1;
    float bv = bias[co];
    u64 aE[TT / 4], aO[TT / 4];
    #pragma unroll
    for (int p = 0; p < TT / 4; p++) { aE[p] = pack2(bv, bv); aO[p] = pack2(bv, bv); }

    const u64* wd = (const u64*)wd_f;
    for (int ci = 0; ci < CIN; ci++) {
        u64 w0 = wd[(ci * 3 + 0) * COUT + co];
        u64 w1 = wd[(ci * 3 + 1) * COUT + co];
        u64 w2 = wd[(ci * 3 + 2) * COUT + co];
        #pragma unroll
        for (int p = 0; p < 4; p++) {
            u64 X = *(const u64*)&s_in[ci][H0 + 2 * p];
            u64 Z = *(const u64*)&s_sh[ci][H0 + 2 * p];
            aE[p] = ffma2(w1, X, aE[p]);
            aO[p] = ffma2(w0, X, aO[p]);
            aO[p] = ffma2(w2, Z, aO[p]);
        }
    }
    long ob = (long)b * oB + (long)co * oCs;
    #pragma unroll
    for (int p = 0; p < 4; p++) {
        float v0 = f2lo(aE[p]), v1 = f2lo(aO[p]), v2 = f2hi(aE[p]), v3 = f2hi(aO[p]);
        if (RELU) { v0 = fmaxf(v0, 0.f); v1 = fmaxf(v1, 0.f); v2 = fmaxf(v2, 0.f); v3 = fmaxf(v3, 0.f); }
        long t = to0 + base + 4 * p;
        out[ob + (t + 0) * oTs] = v0;
        out[ob + (t + 1) * oTs] = v1;
        out[ob + (t + 2) * oTs] = v2;
        out[ob + (t + 3) * oTs] = v3;
    }
}

// ---------------- VQ: mma.sync bf16 SINGLE-pass GEMM + argmax + top-2 margin -------
// CTA = 256 thr (8 warps: 4 x m16, 2 x n32), one batch (64 rows). Grid = 256,
// 2 CTAs/SM. Also emits per-row ||z||^2 and the best score (for loss-from-scores).
#define VQ_A0   0
#define VQ_BOFF 32768
#define VQT_SMEM 98304
#define VQ_BST(stage) (VQ_BOFF + (stage) * 32768)
#define VQ_MARGIN 0.05f

__device__ __forceinline__ void vq_fill_stage(uint32_t smem_base, int stage, int tile,
                                              const __nv_bfloat16* e0, int tid) {
    uint32_t b0 = smem_base + VQ_BST(stage);
    #pragma unroll
    for (int i = 0; i < 8; i++) {
        int c = tid + i * 256;             // 2048 chunks of 16B
        int row = c >> 5, cc = c & 31;
        uint32_t dst = (uint32_t)(row * 512) + (uint32_t)((cc ^ (row & 7)) << 4);
        long srcoff = ((long)tile * 64 + row) * 256 + cc * 8;
        cp_async16(b0 + dst, e0 + srcoff);
    }
}

__global__ __launch_bounds__(256, 2)
void vq_mma_kernel(const float* __restrict__ ze,
                   const __nv_bfloat16* __restrict__ e0,
                   const float* __restrict__ hn, int* __restrict__ out_idx,
                   float* __restrict__ out_score, float* __restrict__ out_zn,
                   int* __restrict__ flag_cnt, int* __restrict__ flag_rows) {
    extern __shared__ char smem[];
    __shared__ float s_znp[256];
    uint32_t smem_base = smem_to_u32(smem);
    int tid = threadIdx.x;
    int cta = blockIdx.x;                   // batch index

    // prefetch B tile 0 (overlaps A conversion)
    vq_fill_stage(smem_base, 0, 0, e0, tid);
    cp_commit();

    // ---- A fill: z -> bf16, swizzled smem; accumulate partial ||z||^2 ----
    {
        int m = tid & 63, kseg = tid >> 6;  // 4 threads per row, 64 k each
        const float* zb = ze + (long)cta * (HD * TQ);
        float zp = 0.f;
        for (int kk = 0; kk < 64; kk++) {
            int k = kseg * 64 + kk;
            float v = zb[k * 64 + m];       // coalesced across m
            zp = fmaf(v, v, zp);
            uint32_t off = (uint32_t)(m * 512) + (uint32_t)((((k >> 3) ^ (m & 7)) << 4) + (k & 7) * 2);
            *(__nv_bfloat16*)(smem + VQ_A0 + off) = __float2bfloat16(v);
        }
        s_znp[tid] = zp;
    }
    asm volatile("cp.async.wait_group 0;" ::: "memory");
    __syncthreads();
    if (tid < 64)
        out_zn[cta * 64 + tid] = s_znp[tid] + s_znp[tid + 64] + s_znp[tid + 128] + s_znp[tid + 192];

    // ---- per-thread fragment address precompute (mapping validated in R11) ----
    int lane = tid & 31, wid = tid >> 5;
    int wm = wid & 3, wn = wid >> 2;
    int mrow = wm * 16 + (lane & 15);
    int khiA = lane >> 4;
    uint32_t aRow = (uint32_t)(mrow * 512);
    int r7A = mrow & 7;
    int nl   = (lane & 7) | ((lane >> 1) & 8);
    int khiB = (lane >> 3) & 1;
    int nrow0 = wn * 32 + nl;
    int nrow1 = nrow0 + 16;
    uint32_t bRow0 = (uint32_t)(nrow0 * 512);
    uint32_t bRow1 = (uint32_t)(nrow1 * 512);
    int r7B0 = nrow0 & 7, r7B1 = nrow1 & 7;

    float best0 = -3.4e38f, sec0 = -3.4e38f, best1 = -3.4e38f, sec1 = -3.4e38f;
    int   idx0 = 0, idx1 = 0;
    const float2* hn2 = (const float2*)hn;

    for (int tile = 0; tile < 128; tile++) {
        int stage = tile & 1;
        if (tile + 1 < 128) {
            vq_fill_stage(smem_base, stage ^ 1, tile + 1, e0, tid);
            cp_commit();
            asm volatile("cp.async.wait_group 1;" ::: "memory");
        } else {
            asm volatile("cp.async.wait_group 0;" ::: "memory");
        }
        __syncthreads();

        uint32_t sb0 = smem_base + VQ_BST(stage);

        float acc[4][4];
        #pragma unroll
        for (int j = 0; j < 4; j++)
            #pragma unroll
            for (int q = 0; q < 4; q++) acc[j][q] = 0.f;

        #pragma unroll
        for (int ks = 0; ks < 16; ks++) {
            uint32_t a0[4], b0[8];
            uint32_t offA = (uint32_t)(((2 * ks + khiA) ^ r7A) << 4);
            ldsm4(a0, smem_base + VQ_A0 + aRow + offA);
            uint32_t cB = (uint32_t)(2 * ks + khiB);
            ldsm4(b0 + 0, sb0 + ((cB ^ (uint32_t)r7B0) << 4) + bRow0);  // n 0-15
            ldsm4(b0 + 4, sb0 + ((cB ^ (uint32_t)r7B1) << 4) + bRow1);  // n 16-31
            mma_bf16(acc[0], a0, b0 + 0);
            mma_bf16(acc[1], a0, b0 + 2);
            mma_bf16(acc[2], a0, b0 + 4);
            mma_bf16(acc[3], a0, b0 + 6);
        }

        // epilogue: scores & top-2 update (ascending n within thread)
        int nb = tile * 64 + wn * 32 + (lane & 3) * 2;
        #pragma unroll
        for (int j = 0; j < 4; j++) {
            int n = nb + j * 8;
            float2 h = __ldg(&hn2[n >> 1]);
            float s0 = acc[j][0] - h.x, s1 = acc[j][1] - h.y;
            float s2 = acc[j][2] - h.x, s3 = acc[j][3] - h.y;
            if (s0 > best0) { sec0 = best0; best0 = s0; idx0 = n; }     else if (s0 > sec0) sec0 = s0;
            if (s1 > best0) { sec0 = best0; best0 = s1; idx0 = n + 1; } else if (s1 > sec0) sec0 = s1;
            if (s2 > best1) { sec1 = best1; best1 = s2; idx1 = n; }     else if (s2 > sec1) sec1 = s2;
            if (s3 > best1) { sec1 = best1; best1 = s3; idx1 = n + 1; } else if (s3 > sec1) sec1 = s3;
        }
        __syncthreads();
    }

    // ---- cross-lane merge within 4-lane row groups ----
    #pragma unroll
    for (int o = 1; o < 4; o <<= 1) {
        float ob = __shfl_xor_sync(0xffffffffu, best0, o);
        float os = __shfl_xor_sync(0xffffffffu, sec0, o);
        int   oi = __shfl_xor_sync(0xffffffffu, idx0, o);
        if (ob > best0)       { sec0 = fmaxf(best0, os); best0 = ob; idx0 = oi; }
        else if (ob == best0) { sec0 = best0; idx0 = min(idx0, oi); }
        else                  { sec0 = fmaxf(sec0, ob); }
        ob = __shfl_xor_sync(0xffffffffu, best1, o);
        os = __shfl_xor_sync(0xffffffffu, sec1, o);
        oi = __shfl_xor_sync(0xffffffffu, idx1, o);
        if (ob > best1)       { sec1 = fmaxf(best1, os); best1 = ob; idx1 = oi; }
        else if (ob == best1) { sec1 = best1; idx1 = min(idx1, oi); }
        else                  { sec1 = fmaxf(sec1, ob); }
    }

    // ---- cross-warp (wn) reduce via smem (A region is free now) ----
    float* rb = (float*)smem;            // [64][2]
    float* rs = rb + 128;                // [64][2]
    int*   ri = (int*)(rb + 256);        // [64][2]
    if ((lane & 3) == 0) {
        int r0 = wm * 16 + (lane >> 2);
        rb[r0 * 2 + wn] = best0; rs[r0 * 2 + wn] = sec0; ri[r0 * 2 + wn] = idx0;
        int r1 = r0 + 8;
        rb[r1 * 2 + wn] = best1; rs[r1 * 2 + wn] = sec1; ri[r1 * 2 + wn] = idx1;
    }
    __syncthreads();
    if (tid < 64) {
        float b = rb[tid * 2], s = rs[tid * 2];
        int   i = ri[tid * 2];
        float ob = rb[tid * 2 + 1], os = rs[tid * 2 + 1];
        int   oi = ri[tid * 2 + 1];
        if (ob > b)       { s = fmaxf(b, os); b = ob; i = oi; }
        else if (ob == b) { s = b; i = min(i, oi); }
        else              { s = fmaxf(s, ob); }
        int gr = cta * 64 + tid;
        out_idx[gr] = i;
        out_score[gr] = b;
        if (b - s < VQ_MARGIN) {
            int sl = atomicAdd(flag_cnt, 1);
            flag_rows[sl] = gr;
        }
    }
}

// ---------------- batched exact fp32 rescore: 8 flagged rows per block ----------------
#define FB_ROWS 8
__global__ __launch_bounds__(256)
void vq_fallback_kernel(const float* __restrict__ ze, const float* __restrict__ emb,
                        const float* __restrict__ hn) {
    int base = blockIdx.x * FB_ROWS;
    int cnt = g_flagcnt[0];
    if (base >= cnt) return;
    __shared__ float zs[256][FB_ROWS];      // [k][row] 8KB
    __shared__ int   rowids[FB_ROWS];
    __shared__ float rv[256];
    __shared__ int   rix[256];
    int tid = threadIdx.x;
    int nrows = min(FB_ROWS, cnt - base);
    if (tid < FB_ROWS)
        rowids[tid] = g_flagrows[base + ((tid < nrows) ? tid : 0)];
    __syncthreads();
    #pragma unroll
    for (int j = 0; j < FB_ROWS; j++) {
        int r = rowids[j];
        int b = r >> 6, t = r & 63;
        zs[tid][j] = ze[(long)b * (HD * TQ) + tid * TQ + t];
    }
    __syncthreads();

    float best[FB_ROWS]; int bidx[FB_ROWS];
    #pragma unroll
    for (int j = 0; j < FB_ROWS; j++) { best[j] = -3.4e38f; bidx[j] = 0; }

    for (int i = 0; i < KC / 256; i++) {
        int n = tid + 256 * i;              // ascending per thread
        const float4* e4 = (const float4*)(emb + (long)n * HD);
        float acc[FB_ROWS];
        #pragma unroll
        for (int j = 0; j < FB_ROWS; j++) acc[j] = 0.f;
        #pragma unroll 4
        for (int k4 = 0; k4 < 64; k4++) {
            float4 ev = e4[k4];
            #pragma unroll
            for (int j = 0; j < FB_ROWS; j++) {
                acc[j] = fmaf(ev.x, zs[4 * k4 + 0][j], acc[j]);
                acc[j] = fmaf(ev.y, zs[4 * k4 + 1][j], acc[j]);
                acc[j] = fmaf(ev.z, zs[4 * k4 + 2][j], acc[j]);
                acc[j] = fmaf(ev.w, zs[4 * k4 + 3][j], acc[j]);
            }
        }
        float h = hn[n];
        #pragma unroll
        for (int j = 0; j < FB_ROWS; j++) {
            float s = acc[j] - h;
            if (s > best[j]) { best[j] = s; bidx[j] = n; }
        }
    }

    // per-row block reduction (lowest index wins ties)
    for (int j = 0; j < FB_ROWS; j++) {
        rv[tid] = best[j]; rix[tid] = bidx[j];
        __syncthreads();
        for (int o = 128; o > 0; o >>= 1) {
            if (tid < o) {
                float v2 = rv[tid + o]; int i2 = rix[tid + o];
                if (v2 > rv[tid] || (v2 == rv[tid] && i2 < rix[tid])) { rv[tid] = v2; rix[tid] = i2; }
            }
            __syncthreads();
        }
        if (tid == 0 && j < nrows) {
            g_idx[rowids[j]] = rix[0];
            g_score[rowids[j]] = rv[0];
        }
        __syncthreads();
    }
}

// ---------------- losses from scores: mean||z-q||^2 = (sum zn - 2*sum score)/N ----
__global__ void lossout_kernel(float* out) {
    __shared__ float red[1024];
    int tid = threadIdx.x;
    float s = 0.f;
    for (int m = tid; m < NB * TQ; m += 1024)
        s += g_zn[m] - 2.f * g_score[m];
    red[tid] = s;
    __syncthreads();
    for (int o = 512; o; o >>= 1) {
        if (tid < o) red[tid] += red[tid + o];
        __syncthreads();
    }
    if (tid == 0) {
        float l = red[0] * (1.f / 4194304.f);
        out[LOSS_OFF + 0] = l;
        out[LOSS_OFF + 1] = l;
    }
}

// ---------------- indices to output ----------------
__global__ void idxout_kernel(float* out) {
    int m = blockIdx.x * 256 + threadIdx.x;
    out[IDX_OFF + m] = (float)g_idx[m];
}

// ---------------- launch ----------------
extern "C" void kernel_launch(void* const* d_in, const int* in_sizes, int n_in,
                              void* d_out, int out_size) {
    const float* x   = (const float*)d_in[0];
    const float* ew0 = (const float*)d_in[1];  const float* eb0b = (const float*)d_in[2];
    const float* ew1 = (const float*)d_in[3];  const float* eb1b = (const float*)d_in[4];
    const float* ew2 = (const float*)d_in[5];  const float* eb2b = (const float*)d_in[6];
    const float* pw  = (const float*)d_in[7];  const float* pb   = (const float*)d_in[8];
    const float* emb = (const float*)d_in[9];
    const float* dw0 = (const float*)d_in[10]; const float* db0 = (const float*)d_in[11];
    const float* dw1 = (const float*)d_in[12]; const float* db1 = (const float*)d_in[13];
    const float* dw2 = (const float*)d_in[14]; const float* db2 = (const float*)d_in[15];
    const float* dw3 = (const float*)d_in[16]; const float* db3 = (const float*)d_in[17];
    float* out = (float*)d_out;

    void* p;
    cudaGetSymbolAddress(&p, g_wt);   float* wt  = (float*)p;
    cudaGetSymbolAddress(&p, g_wtd);  float* wtd = (float*)p;
    cudaGetSymbolAddress(&p, g_eb0);  __nv_bfloat16* e0 = (__nv_bfloat16*)p;
    cudaGetSymbolAddress(&p, g_h0);   float* h0  = (float*)p;
    cudaGetSymbolAddress(&p, g_h1);   float* h1  = (float*)p;
    cudaGetSymbolAddress(&p, g_h2);   float* h2  = (float*)p;
    cudaGetSymbolAddress(&p, g_ze);   float* ze  = (float*)p;
    cudaGetSymbolAddress(&p, g_d0);   float* d0  = (float*)p;
    cudaGetSymbolAddress(&p, g_d1);   float* d1  = (float*)p;
    cudaGetSymbolAddress(&p, g_d2);   float* d2  = (float*)p;
    cudaGetSymbolAddress(&p, g_hn);   float* hn  = (float*)p;
    cudaGetSymbolAddress(&p, g_idx);  int*   ix  = (int*)p;
    cudaGetSymbolAddress(&p, g_score); float* sc = (float*)p;
    cudaGetSymbolAddress(&p, g_zn);   float* zn  = (float*)p;
    cudaGetSymbolAddress(&p, g_flagcnt);  int* fcnt = (int*)p;
    cudaGetSymbolAddress(&p, g_flagrows); int* frow = (int*)p;

    cudaFuncSetAttribute(vq_mma_kernel, cudaFuncAttributeMaxDynamicSharedMemorySize, VQT_SMEM);

    // prep
    WtArgs wa;
    const float* srcs[8] = {ew0, ew1, ew2, pw, dw0, dw1, dw2, dw3};
    int offs[8]  = {WT0, WT1, WT2, WTP, WD0, WD1, WD2, WD3};
    int couts[8] = {64, 128, 256, 256, 256, 128, 64, 32};
    int cinks[8] = {32*3, 64*3, 128*3, 256, 256*3, 256*3, 128*3, 64*3};
    int acc = 0;
    for (int q = 0; q < 8; q++) {
        wa.src[q] = srcs[q]; wa.dst_off[q] = offs[q];
        wa.cout[q] = couts[q]; wa.cink[q] = cinks[q];
        wa.start[q] = acc; acc += couts[q] * cinks[q];
    }
    wa.total = acc;
    wtrans_all_kernel<<<(acc + 255) / 256, 256>>>(wa, wt, wtd);
    ebnorm_kernel<<<KC/8, 256>>>(emb, e0);

    // encoder (conv0: channel-contiguous input -> CFIRST fill, TT=32)
    conv1d_kernel<32, 64, 32, 2, 1, true, true ><<<dim3(NB, 8), 64 >>>(x,  wt+WT0, eb0b, h0, 512, 256, 512*32, 1,  32);
    conv1d_kernel<64, 128,16, 2, 1, true, false><<<dim3(NB, 8), 128>>>(h0, wt+WT1, eb1b, h1, 256, 128, 64*256, 256, 1);
    conv1d_kernel<128,256,16, 2, 1, true, false><<<dim3(NB, 4), 256>>>(h1, wt+WT2, eb2b, h2, 128, 64,  128*128,128, 1);
    proj_kernel<<<dim3(NB, 4), 256>>>(h2, wt+WTP, pb, ze);

    // vector quantizer (tensor core single-pass + batched exact fallback)
    vq_mma_kernel<<<NB, 256, VQT_SMEM>>>(ze, e0, hn, ix, sc, zn, fcnt, frow);
    vq_fallback_kernel<<<16384 / FB_ROWS, 256>>>(ze, emb, hn);
    lossout_kernel<<<1, 1024>>>(out);
    idxout_kernel<<<64, 256>>>(out);

    // decoder (dec0 gathers z_q = emb[idx] directly)
    deconv1d_kernel<256,256,16,1, true, true ><<<dim3(NB, 8), dim3(256,1)>>>(nullptr, wtd+WD0, db0, d0, 64,  256*128, 128, 1, ix, emb);
    deconv1d_kernel<256,128,16,1, true, false><<<dim3(NB,16), dim3(128,1)>>>(d0, wtd+WD1, db1, d1, 128, 128*256, 256, 1, nullptr, nullptr);
    deconv1d_kernel<128,64, 16,2, true, false><<<dim3(NB,16), dim3(64, 2)>>>(d1, wtd+WD2, db2, d2, 256, 64*512,  512, 1, nullptr, nullptr);
    deconv1d_kernel<64, 32, 16,4, false,false><<<dim3(NB,16), dim3(32, 4)>>>(d2, wtd+WD3, db3, out,512, 1024*32, 1,  32, nullptr, nullptr);
}

// round 16
// speedup vs baseline: 8.4157x; 1.2754x over previous
#include <cuda_runtime.h>
#include <cuda_bf16.h>
#include <cstdint>

// ---------------- problem constants ----------------
#define NB   256      // batch
#define TQ   64       // quantized time
#define HD   256      // hidden dim
#define KC   8192     // n_embeddings

// output packing: (out, codebook_loss, commitment_loss, indices)
#define OUT_ELEMS   (256*1024*32)      // 8388608
#define LOSS_OFF    OUT_ELEMS
#define IDX_OFF     (OUT_ELEMS + 2)

// encoder/proj transposed-weight offsets (in g_wt)
#define WT0  0
#define WT1  6144
#define WT2  30720
#define WTP  129024
#define WT_TOT 194560

// deconv duplicated-weight offsets (in g_wtd) — dec2/dec3 only now
#define WD2  0          // 128*3*64*2 = 49152
#define WD3  49152      // 64*3*32*2  = 12288
#define WD_TOT 61440

typedef unsigned long long u64;

// ---------------- f32x2 helpers ----------------
__device__ __forceinline__ u64 ffma2(u64 a, u64 b, u64 c) {
    u64 d;
    asm("fma.rn.f32x2 %0, %1, %2, %3;" : "=l"(d) : "l"(a), "l"(b), "l"(c));
    return d;
}
__device__ __forceinline__ u64 pack2(float lo, float hi) {
    u64 d;
    asm("mov.b64 %0, {%1, %2};" : "=l"(d) : "f"(lo), "f"(hi));
    return d;
}
__device__ __forceinline__ float f2lo(u64 v) {
    float lo, hi; asm("mov.b64 {%0, %1}, %2;" : "=f"(lo), "=f"(hi) : "l"(v)); return lo;
}
__device__ __forceinline__ float f2hi(u64 v) {
    float lo, hi; asm("mov.b64 {%0, %1}, %2;" : "=f"(lo), "=f"(hi) : "l"(v)); return hi;
}
__device__ __forceinline__ void cp_async16(unsigned smem_addr, const void* gptr) {
    asm volatile("cp.async.cg.shared.global [%0], [%1], 16;" :: "r"(smem_addr), "l"(gptr));
}
__device__ __forceinline__ void cp_commit() { asm volatile("cp.async.commit_group;" ::: "memory"); }

// ---------------- mma.sync helpers (sm_80-era, valid on baseline sm_103) ----------
__device__ __forceinline__ uint32_t smem_to_u32(const void* smem_ptr) {
    uint32_t addr;
    asm("{ .reg .u64 tmp; cvta.to.shared.u64 tmp, %1; cvt.u32.u64 %0, tmp; }"
        : "=r"(addr) : "l"(smem_ptr));
    return addr;
}
__device__ __forceinline__ void ldsm4(uint32_t* r, uint32_t addr) {
    asm volatile("ldmatrix.sync.aligned.m8n8.x4.shared.b16 {%0,%1,%2,%3}, [%4];"
        : "=r"(r[0]), "=r"(r[1]), "=r"(r[2]), "=r"(r[3]) : "r"(addr));
}
__device__ __forceinline__ void mma_bf16(float* c, const uint32_t* a, const uint32_t* b) {
    asm volatile(
        "mma.sync.aligned.m16n8k16.row.col.f32.bf16.bf16.f32 "
        "{%0,%1,%2,%3}, {%4,%5,%6,%7}, {%8,%9}, {%0,%1,%2,%3};"
        : "+f"(c[0]), "+f"(c[1]), "+f"(c[2]), "+f"(c[3])
        : "r"(a[0]), "r"(a[1]), "r"(a[2]), "r"(a[3]), "r"(b[0]), "r"(b[1]));
}

// ---------------- device scratch ----------------
__device__ float g_h0[256*64*256];
__device__ float g_h1[256*128*128];
__device__ float g_h2[256*256*64];
__device__ float g_ze[256*256*64];
__device__ float g_Y0[16384*768];           // dec0 GEMM scores
__device__ float g_Y1[32768*384];           // dec1 GEMM scores
__device__ float g_d2[256*64*512];
__device__ float g_wt[WT_TOT];
__device__ float g_wtd[WD_TOT];
__device__ __nv_bfloat16 g_eb0[8192*256];   // codebook bf16 [n][k]
__device__ __nv_bfloat16 g_wc0h[768*256];   // dec0 W_cat hi split [n][k]
__device__ __nv_bfloat16 g_wc0l[768*256];   // dec0 W_cat lo split
__device__ __nv_bfloat16 g_wc1h[384*256];   // dec1 W_cat hi split
__device__ __nv_bfloat16 g_wc1l[384*256];   // dec1 W_cat lo split
__device__ float g_hn[KC];
__device__ int   g_idx[NB*TQ];
__device__ float g_score[NB*TQ];
__device__ float g_zn[NB*TQ];
__device__ int   g_flagcnt[1];
__device__ int   g_flagrows[16384];

// ---------------- combined weight transpose (enc + dec2/dec3 only) ----------------
struct WtArgs {
    const float* src[8];
    int dst_off[8];
    int cout[8];
    int cink[8];
    int start[8];
    int total;
};
__global__ void wtrans_all_kernel(WtArgs a, float* __restrict__ wt, float* __restrict__ wtd) {
    int i = blockIdx.x * 256 + threadIdx.x;
    if (i >= a.total) return;
    int s = 0;
    #pragma unroll
    for (int q = 1; q < 8; q++) if (i >= a.start[q]) s = q;
    int e  = i - a.start[s];
    int co = e / a.cink[s];
    int r  = e - co * a.cink[s];
    float v = a.src[s][e];
    if (s < 4) {
        wt[a.dst_off[s] + r * a.cout[s] + co] = v;
    } else {
        int o = a.dst_off[s] + (r * a.cout[s] + co) * 2;
        wtd[o] = v; wtd[o + 1] = v;
    }
}

// ---------------- W_cat bf16 split build for dec0/dec1 GEMMs ----------------
// W_cat rows: [0,C): tap1 (even); [C,2C): tap0 (odd lo); [2C,3C): tap2 (odd hi).
__global__ void wcat_kernel(const float* __restrict__ dw0, const float* __restrict__ dw1) {
    int i = blockIdx.x * 256 + threadIdx.x;   // total 1152*256
    const int T0 = 768 * 256;
    float v; long o;
    __nv_bfloat16 *dh, *dl;
    if (i < T0) {
        int n = i >> 8, k = i & 255;
        int blk = n >> 8, co = n & 255;
        int tap = (blk == 0) ? 1 : ((blk == 1) ? 0 : 2);
        v = dw0[(co * 256 + k) * 3 + tap];
        dh = g_wc0h; dl = g_wc0l; o = i;
    } else {
        int i2 = i - T0;
        if (i2 >= 384 * 256) return;
        int n = i2 >> 8, k = i2 & 255;
        int blk = n >> 7, co = n & 127;
        int tap = (blk == 0) ? 1 : ((blk == 1) ? 0 : 2);
        v = dw1[(co * 256 + k) * 3 + tap];
        dh = g_wc1h; dl = g_wc1l; o = i2;
    }
    __nv_bfloat16 h = __float2bfloat16(v);
    dh[o] = h;
    dl[o] = __float2bfloat16(v - __bfloat162float(h));
}

// ---------------- codebook: 0.5*||e||^2 + bf16 convert (one pass) ----------------
__global__ void ebnorm_kernel(const float* __restrict__ emb, __nv_bfloat16* __restrict__ e0) {
    if (blockIdx.x == 0 && threadIdx.x == 0) g_flagcnt[0] = 0;
    int n = blockIdx.x * 8 + (threadIdx.x >> 5);
    int lane = threadIdx.x & 31;
    const float* e = emb + (long)n * HD;
    __nv_bfloat16* eo = e0 + (long)n * HD;
    float s = 0.f;
    #pragma unroll
    for (int c = lane; c < HD; c += 32) {
        float v = e[c];
        s += v * v;
        eo[c] = __float2bfloat16(v);
    }
    #pragma unroll
    for (int o = 16; o; o >>= 1) s += __shfl_xor_sync(0xffffffffu, s, o);
    if (lane == 0) g_hn[n] = 0.5f * s;
}

// ---------------- generic direct conv1d (k=3, strided; encoder) ----------------
template<int CIN, int COUT, int TT, int STRIDE, int PAD, bool RELU, bool CFIRST>
__global__ void conv1d_kernel(const float* __restrict__ in, const float* __restrict__ wt,
                              const float* __restrict__ bias, float* __restrict__ out,
                              int Tin, int Tout, int inB, int inC, int inT) {
    const int SW = STRIDE * (TT - 1) + 3;
    __shared__ float s_in[CIN][SW];
    int b   = blockIdx.x;
    int to0 = blockIdx.y * TT;
    int ti0 = STRIDE * to0 - PAD;

    for (int idx = threadIdx.x; idx < CIN * SW; idx += blockDim.x) {
        int ci, j;
        if (CFIRST) { ci = idx % CIN; j = idx / CIN; }
        else        { ci = idx / SW;  j = idx - ci * SW; }
        int tg = ti0 + j;
        s_in[ci][j] = (tg >= 0 && tg < Tin)
            ? in[(long)b * inB + (long)ci * inC + (long)tg * inT] : 0.f;
    }
    __syncthreads();

    int co = threadIdx.x;
    float acc[TT];
    float bv = bias[co];
    #pragma unroll
    for (int t = 0; t < TT; t++) acc[t] = bv;

    for (int ci = 0; ci < CIN; ci++) {
        const float* sr = s_in[ci];
        float w0 = wt[(ci * 3 + 0) * COUT + co];
        float w1 = wt[(ci * 3 + 1) * COUT + co];
        float w2 = wt[(ci * 3 + 2) * COUT + co];
        #pragma unroll
        for (int t = 0; t < TT; t++) {
            acc[t] = fmaf(w0, sr[STRIDE * t + 0], acc[t]);
            acc[t] = fmaf(w1, sr[STRIDE * t + 1], acc[t]);
            acc[t] = fmaf(w2, sr[STRIDE * t + 2], acc[t]);
        }
    }
    long ob = (long)b * COUT * Tout + (long)co * Tout + to0;
    #pragma unroll
    for (int t = 0; t < TT; t++) {
        float v = acc[t];
        if (RELU) v = fmaxf(v, 0.f);
        out[ob + t] = v;
    }
}

// ---------------- 1x1 projection conv, f32x2 ----------------
__global__ void proj_kernel(const float* __restrict__ in, const float* __restrict__ wt,
                            const float* __restrict__ bias, float* __restrict__ out) {
    __shared__ float s_in[256][16];
    int b   = blockIdx.x;
    int to0 = blockIdx.y * 16;
    for (int idx = threadIdx.x; idx < 256 * 16; idx += 256) {
        int ci = idx >> 4, j = idx & 15;
        s_in[ci][j] = in[(long)b * (256 * 64) + ci * 64 + to0 + j];
    }
    __syncthreads();

    int co = threadIdx.x;
    float bv = bias[co];
    u64 acc[8];
    #pragma unroll
    for (int p = 0; p < 8; p++) acc[p] = pack2(bv, bv);

    for (int ci = 0; ci < 256; ci++) {
        float w = wt[ci * 256 + co];
        u64 ws = pack2(w, w);
        const u64* xr = (const u64*)&s_in[ci][0];
        #pragma unroll
        for (int p = 0; p < 8; p++) acc[p] = ffma2(ws, xr[p], acc[p]);
    }
    long ob = (long)b * (256 * 64) + (long)co * 64 + to0;
    #pragma unroll
    for (int p = 0; p < 8; p++) {
        out[ob + 2 * p + 0] = f2lo(acc[p]);
        out[ob + 2 * p + 1] = f2hi(acc[p]);
    }
}

// ---------------- deconv (k=3 s=2 p=1 op=1), f32x2, dup weights ----------------
// MODE 0: read `in` [b][ci][t]. MODE 2: build input from GEMM scores ysrc
// (ycols=3*CIN): even t: ysrc[r][ci]; odd t: ysrc[r][CIN+ci]+ysrc[r+1][2CIN+ci];
// r = b*(Tin/2)+t/2; then relu(+pbias[ci]).
template<int CIN, int COUT, int TT, int G, bool RELU, int MODE>
__global__ void deconv1d_kernel(const float* __restrict__ in, const float* __restrict__ wd_f,
                                const float* __restrict__ bias, float* __restrict__ out,
                                int Tin, long oB, long oCs, long oTs,
                                const float* __restrict__ ysrc, const float* __restrict__ pbias) {
    const int IW  = G * TT / 2 + 1;
    const int IWP = (IW | 1) + 1;
    const int IWL = IW + 1;
    __shared__ float s_in[CIN][IWP];
    __shared__ float s_sh[CIN][IWP];
    int b   = blockIdx.x;
    int to0 = blockIdx.y * (G * TT);
    int t0h = to0 >> 1;
    int nt  = blockDim.x * blockDim.y;
    int tid = threadIdx.y * blockDim.x + threadIdx.x;

    if (MODE == 2) {
        const int YC = 3 * CIN;
        int halfT = Tin >> 1;
        for (int idx = tid; idx < CIN * IWL; idx += nt) {
            int ci = idx % CIN, j = idx / CIN;    // ci fastest: coalesced ysrc reads
            int tg = t0h + j;
            float v = 0.f;
            if (tg < Tin) {
                long r = (long)b * halfT + (tg >> 1);
                if (!(tg & 1)) v = ysrc[r * YC + ci];
                else {
                    v = ysrc[r * YC + CIN + ci];
                    if ((tg >> 1) + 1 < halfT) v += ysrc[(r + 1) * YC + 2 * CIN + ci];
                }
                v = fmaxf(v + pbias[ci], 0.f);
            }
            if (j < IW) s_in[ci][j] = v;
            if (j > 0)  s_sh[ci][j - 1] = v;
        }
    } else {
        for (int idx = tid; idx < CIN * IWL; idx += nt) {
            int ci = idx / IWL, j = idx - ci * IWL;
            int tg = t0h + j;
            float v = (tg < Tin) ? in[(long)b * CIN * Tin + (long)ci * Tin + tg] : 0.f;
            if (j < IW) s_in[ci][j] = v;
            if (j > 0)  s_sh[ci][j - 1] = v;
        }
    }
    __syncthreads();

    int co   = threadIdx.x;
    int base = threadIdx.y * TT;
    int H0   = base >> 1;
    float bv = bias[co];
    u64 aE[TT / 4], aO[TT / 4];
    #pragma unroll
    for (int p = 0; p < TT / 4; p++) { aE[p] = pack2(bv, bv); aO[p] = pack2(bv, bv); }

    const u64* wd = (const u64*)wd_f;
    for (int ci = 0; ci < CIN; ci++) {
        u64 w0 = wd[(ci * 3 + 0) * COUT + co];
        u64 w1 = wd[(ci * 3 + 1) * COUT + co];
        u64 w2 = wd[(ci * 3 + 2) * COUT + co];
        #pragma unroll
        for (int p = 0; p < 4; p++) {
            u64 X = *(const u64*)&s_in[ci][H0 + 2 * p];
            u64 Z = *(const u64*)&s_sh[ci][H0 + 2 * p];
            aE[p] = ffma2(w1, X, aE[p]);
            aO[p] = ffma2(w0, X, aO[p]);
            aO[p] = ffma2(w2, Z, aO[p]);
        }
    }
    long ob = (long)b * oB + (long)co * oCs;
    #pragma unroll
    for (int p = 0; p < 4; p++) {
        float v0 = f2lo(aE[p]), v1 = f2lo(aO[p]), v2 = f2hi(aE[p]), v3 = f2hi(aO[p]);
        if (RELU) { v0 = fmaxf(v0, 0.f); v1 = fmaxf(v1, 0.f); v2 = fmaxf(v2, 0.f); v3 = fmaxf(v3, 0.f); }
        long t = to0 + base + 4 * p;
        out[ob + (t + 0) * oTs] = v0;
        out[ob + (t + 1) * oTs] = v1;
        out[ob + (t + 2) * oTs] = v2;
        out[ob + (t + 3) * oTs] = v3;
    }
}

// ================= decoder GEMM (mma.sync bf16 3-pass split) =================
// A (64 rows x 256 k) from either emb-gather (dec0) or fused Y0 epilogue (dec1).
// B = W_cat splits, N-tiles of 64, double-buffered. Writes raw fp32 scores to Y.
#define GD_A0   0
#define GD_A1   32768
#define GD_BOFF 65536
#define GD_SMEM 196608
#define GD_BST(stage) (GD_BOFF + (stage) * 65536)

__device__ __forceinline__ void gd_fill(uint32_t smem_base, int stage, int tile,
                                        const __nv_bfloat16* wh, const __nv_bfloat16* wl,
                                        int tid) {
    uint32_t bh = smem_base + GD_BST(stage);
    uint32_t bl = bh + 32768;
    #pragma unroll
    for (int i = 0; i < 8; i++) {
        int c = tid + i * 256;
        int row = c >> 5, cc = c & 31;
        uint32_t dst = (uint32_t)(row * 512) + (uint32_t)((cc ^ (row & 7)) << 4);
        long srcoff = ((long)tile * 64 + row) * 256 + cc * 8;
        cp_async16(bh + dst, wh + srcoff);
        cp_async16(bl + dst, wl + srcoff);
    }
}
__device__ __forceinline__ void gd_store_a(char* smem, int m, int k, float v) {
    uint32_t off = (uint32_t)(m * 512) + (uint32_t)((((k >> 3) ^ (m & 7)) << 4) + (k & 7) * 2);
    __nv_bfloat16 h = __float2bfloat16(v);
    *(__nv_bfloat16*)(smem + GD_A0 + off) = h;
    *(__nv_bfloat16*)(smem + GD_A1 + off) = __float2bfloat16(v - __bfloat162float(h));
}

template<bool GATHER, int NT, int CTAS_PER_B>
__global__ __launch_bounds__(256, 1)
void gemm_dec_kernel(const int* __restrict__ eidx, const float* __restrict__ emb,
                     const float* __restrict__ ysrc, const float* __restrict__ pbias,
                     const __nv_bfloat16* __restrict__ wh, const __nv_bfloat16* __restrict__ wl,
                     float* __restrict__ yout) {
    const int NCAT = NT * 64;
    const int TIN  = 64 * CTAS_PER_B;
    extern __shared__ char smem[];
    __shared__ int s_e[64];
    uint32_t smem_base = smem_to_u32(smem);
    int tid = threadIdx.x;
    int b   = blockIdx.x / CTAS_PER_B;
    int j0  = (blockIdx.x % CTAS_PER_B) * 64;

    gd_fill(smem_base, 0, 0, wh, wl, tid);
    cp_commit();

    // ---- A fill (bf16 split, swizzled) ----
    if (GATHER) {
        if (tid < 64) s_e[tid] = eidx[b * 64 + tid];
        __syncthreads();
        int m = tid >> 2, ks = tid & 3;
        const float* er = emb + (long)s_e[m] * 256 + ks * 64;
        #pragma unroll 4
        for (int kk = 0; kk < 64; kk++)
            gd_store_a(smem, m, ks * 64 + kk, er[kk]);
    } else {
        // A[m][k] = relu(pbias[k] + evens/odds from ysrc rows), t = j0+m, k = tid
        int k = tid;
        float bv = pbias[k];
        const int halfT = 64;               // Y0 rows per batch (dec0 Tin=64)
        for (int m = 0; m < 64; m++) {
            int t = j0 + m;
            long r = (long)b * halfT + (t >> 1);
            float v;
            if (!(t & 1)) v = ysrc[r * 768 + k];
            else {
                v = ysrc[r * 768 + 256 + k];
                if ((t >> 1) + 1 < halfT) v += ysrc[(r + 1) * 768 + 512 + k];
            }
            gd_store_a(smem, m, k, fmaxf(v + bv, 0.f));
        }
    }
    asm volatile("cp.async.wait_group 0;" ::: "memory");
    __syncthreads();

    // ---- fragment addressing (validated mapping) ----
    int lane = tid & 31, wid = tid >> 5;
    int wm = wid & 3, wn = wid >> 2;
    int mrow = wm * 16 + (lane & 15);
    int khiA = lane >> 4;
    uint32_t aRow = (uint32_t)(mrow * 512);
    int r7A = mrow & 7;
    int nl   = (lane & 7) | ((lane >> 1) & 8);
    int khiB = (lane >> 3) & 1;
    int nrow0 = wn * 32 + nl;
    int nrow1 = nrow0 + 16;
    uint32_t bRow0 = (uint32_t)(nrow0 * 512);
    uint32_t bRow1 = (uint32_t)(nrow1 * 512);
    int r7B0 = nrow0 & 7, r7B1 = nrow1 & 7;

    long rowg0 = ((long)b * TIN + j0 + wm * 16 + (lane >> 2)) * NCAT;
    long rowg1 = rowg0 + 8L * NCAT;
    int  colg  = wn * 32 + (lane & 3) * 2;

    for (int nt = 0; nt < NT; nt++) {
        int stage = nt & 1;
        if (nt + 1 < NT) {
            gd_fill(smem_base, stage ^ 1, nt + 1, wh, wl, tid);
            cp_commit();
            asm volatile("cp.async.wait_group 1;" ::: "memory");
        } else {
            asm volatile("cp.async.wait_group 0;" ::: "memory");
        }
        __syncthreads();

        uint32_t sbh = smem_base + GD_BST(stage);
        uint32_t sbl = sbh + 32768;

        float acc[4][4];
        #pragma unroll
        for (int j = 0; j < 4; j++)
            #pragma unroll
            for (int q = 0; q < 4; q++) acc[j][q] = 0.f;

        #pragma unroll
        for (int ks = 0; ks < 16; ks++) {
            uint32_t a0[4], a1[4], bh[8], bl[8];
            uint32_t offA = (uint32_t)(((2 * ks + khiA) ^ r7A) << 4);
            ldsm4(a0, smem_base + GD_A0 + aRow + offA);
            ldsm4(a1, smem_base + GD_A1 + aRow + offA);
            uint32_t cB = (uint32_t)(2 * ks + khiB);
            uint32_t oB0 = ((cB ^ (uint32_t)r7B0) << 4) + bRow0;
            uint32_t oB1 = ((cB ^ (uint32_t)r7B1) << 4) + bRow1;
            ldsm4(bh + 0, sbh + oB0);
            ldsm4(bh + 4, sbh + oB1);
            ldsm4(bl + 0, sbl + oB0);
            ldsm4(bl + 4, sbl + oB1);
            #pragma unroll
            for (int j = 0; j < 4; j++) {
                mma_bf16(acc[j], a0, bh + 2 * j);
                mma_bf16(acc[j], a1, bh + 2 * j);
                mma_bf16(acc[j], a0, bl + 2 * j);
            }
        }

        // write raw scores
        int cb = nt * 64 + colg;
        #pragma unroll
        for (int j = 0; j < 4; j++) {
            *(float2*)&yout[rowg0 + cb + j * 8] = make_float2(acc[j][0], acc[j][1]);
            *(float2*)&yout[rowg1 + cb + j * 8] = make_float2(acc[j][2], acc[j][3]);
        }
        __syncthreads();
    }
}

// ---------------- VQ: mma.sync bf16 SINGLE-pass GEMM + argmax + top-2 margin -------
#define VQ_A0   0
#define VQ_BOFF 32768
#define VQT_SMEM 98304
#define VQ_BST(stage) (VQ_BOFF + (stage) * 32768)
#define VQ_MARGIN 0.05f

__device__ __forceinline__ void vq_fill_stage(uint32_t smem_base, int stage, int tile,
                                              const __nv_bfloat16* e0, int tid) {
    uint32_t b0 = smem_base + VQ_BST(stage);
    #pragma unroll
    for (int i = 0; i < 8; i++) {
        int c = tid + i * 256;
        int row = c >> 5, cc = c & 31;
        uint32_t dst = (uint32_t)(row * 512) + (uint32_t)((cc ^ (row & 7)) << 4);
        long srcoff = ((long)tile * 64 + row) * 256 + cc * 8;
        cp_async16(b0 + dst, e0 + srcoff);
    }
}

__global__ __launch_bounds__(256, 2)
void vq_mma_kernel(const float* __restrict__ ze,
                   const __nv_bfloat16* __restrict__ e0,
                   const float* __restrict__ hn, int* __restrict__ out_idx,
                   float* __restrict__ out_score, float* __restrict__ out_zn,
                   int* __restrict__ flag_cnt, int* __restrict__ flag_rows) {
    extern __shared__ char smem[];
    __shared__ float s_znp[256];
    uint32_t smem_base = smem_to_u32(smem);
    int tid = threadIdx.x;
    int cta = blockIdx.x;

    vq_fill_stage(smem_base, 0, 0, e0, tid);
    cp_commit();

    {
        int m = tid & 63, kseg = tid >> 6;
        const float* zb = ze + (long)cta * (HD * TQ);
        float zp = 0.f;
        for (int kk = 0; kk < 64; kk++) {
            int k = kseg * 64 + kk;
            float v = zb[k * 64 + m];
            zp = fmaf(v, v, zp);
            uint32_t off = (uint32_t)(m * 512) + (uint32_t)((((k >> 3) ^ (m & 7)) << 4) + (k & 7) * 2);
            *(__nv_bfloat16*)(smem + VQ_A0 + off) = __float2bfloat16(v);
        }
        s_znp[tid] = zp;
    }
    asm volatile("cp.async.wait_group 0;" ::: "memory");
    __syncthreads();
    if (tid < 64)
        out_zn[cta * 64 + tid] = s_znp[tid] + s_znp[tid + 64] + s_znp[tid + 128] + s_znp[tid + 192];

    int lane = tid & 31, wid = tid >> 5;
    int wm = wid & 3, wn = wid >> 2;
    int mrow = wm * 16 + (lane & 15);
    int khiA = lane >> 4;
    uint32_t aRow = (uint32_t)(mrow * 512);
    int r7A = mrow & 7;
    int nl   = (lane & 7) | ((lane >> 1) & 8);
    int khiB = (lane >> 3) & 1;
    int nrow0 = wn * 32 + nl;
    int nrow1 = nrow0 + 16;
    uint32_t bRow0 = (uint32_t)(nrow0 * 512);
    uint32_t bRow1 = (uint32_t)(nrow1 * 512);
    int r7B0 = nrow0 & 7, r7B1 = nrow1 & 7;

    float best0 = -3.4e38f, sec0 = -3.4e38f, best1 = -3.4e38f, sec1 = -3.4e38f;
    int   idx0 = 0, idx1 = 0;
    const float2* hn2 = (const float2*)hn;

    for (int tile = 0; tile < 128; tile++) {
        int stage = tile & 1;
        if (tile + 1 < 128) {
            vq_fill_stage(smem_base, stage ^ 1, tile + 1, e0, tid);
            cp_commit();
            asm volatile("cp.async.wait_group 1;" ::: "memory");
        } else {
            asm volatile("cp.async.wait_group 0;" ::: "memory");
        }
        __syncthreads();

        uint32_t sb0 = smem_base + VQ_BST(stage);

        float acc[4][4];
        #pragma unroll
        for (int j = 0; j < 4; j++)
            #pragma unroll
            for (int q = 0; q < 4; q++) acc[j][q] = 0.f;

        #pragma unroll
        for (int ks = 0; ks < 16; ks++) {
            uint32_t a0[4], b0[8];
            uint32_t offA = (uint32_t)(((2 * ks + khiA) ^ r7A) << 4);
            ldsm4(a0, smem_base + VQ_A0 + aRow + offA);
            uint32_t cB = (uint32_t)(2 * ks + khiB);
            ldsm4(b0 + 0, sb0 + ((cB ^ (uint32_t)r7B0) << 4) + bRow0);
            ldsm4(b0 + 4, sb0 + ((cB ^ (uint32_t)r7B1) << 4) + bRow1);
            mma_bf16(acc[0], a0, b0 + 0);
            mma_bf16(acc[1], a0, b0 + 2);
            mma_bf16(acc[2], a0, b0 + 4);
            mma_bf16(acc[3], a0, b0 + 6);
        }

        int nb = tile * 64 + wn * 32 + (lane & 3) * 2;
        #pragma unroll
        for (int j = 0; j < 4; j++) {
            int n = nb + j * 8;
            float2 h = __ldg(&hn2[n >> 1]);
            float s0 = acc[j][0] - h.x, s1 = acc[j][1] - h.y;
            float s2 = acc[j][2] - h.x, s3 = acc[j][3] - h.y;
            if (s0 > best0) { sec0 = best0; best0 = s0; idx0 = n; }     else if (s0 > sec0) sec0 = s0;
            if (s1 > best0) { sec0 = best0; best0 = s1; idx0 = n + 1; } else if (s1 > sec0) sec0 = s1;
            if (s2 > best1) { sec1 = best1; best1 = s2; idx1 = n; }     else if (s2 > sec1) sec1 = s2;
            if (s3 > best1) { sec1 = best1; best1 = s3; idx1 = n + 1; } else if (s3 > sec1) sec1 = s3;
        }
        __syncthreads();
    }

    #pragma unroll
    for (int o = 1; o < 4; o <<= 1) {
        float ob = __shfl_xor_sync(0xffffffffu, best0, o);
        float os = __shfl_xor_sync(0xffffffffu, sec0, o);
        int   oi = __shfl_xor_sync(0xffffffffu, idx0, o);
        if (ob > best0)       { sec0 = fmaxf(best0, os); best0 = ob; idx0 = oi; }
        else if (ob == best0) { sec0 = best0; idx0 = min(idx0, oi); }
        else                  { sec0 = fmaxf(sec0, ob); }
        ob = __shfl_xor_sync(0xffffffffu, best1, o);
        os = __shfl_xor_sync(0xffffffffu, sec1, o);
        oi = __shfl_xor_sync(0xffffffffu, idx1, o);
        if (ob > best1)       { sec1 = fmaxf(best1, os); best1 = ob; idx1 = oi; }
        else if (ob == best1) { sec1 = best1; idx1 = min(idx1, oi); }
        else                  { sec1 = fmaxf(sec1, ob); }
    }

    float* rb = (float*)smem;
    float* rs = rb + 128;
    int*   ri = (int*)(rb + 256);
    if ((lane & 3) == 0) {
        int r0 = wm * 16 + (lane >> 2);
        rb[r0 * 2 + wn] = best0; rs[r0 * 2 + wn] = sec0; ri[r0 * 2 + wn] = idx0;
        int r1 = r0 + 8;
        rb[r1 * 2 + wn] = best1; rs[r1 * 2 + wn] = sec1; ri[r1 * 2 + wn] = idx1;
    }
    __syncthreads();
    if (tid < 64) {
        float b = rb[tid * 2], s = rs[tid * 2];
        int   i = ri[tid * 2];
        float ob = rb[tid * 2 + 1], os = rs[tid * 2 + 1];
        int   oi = ri[tid * 2 + 1];
        if (ob > b)       { s = fmaxf(b, os); b = ob; i = oi; }
        else if (ob == b) { s = b; i = min(i, oi); }
        else              { s = fmaxf(s, ob); }
        int gr = cta * 64 + tid;
        out_idx[gr] = i;
        out_score[gr] = b;
        if (b - s < VQ_MARGIN) {
            int sl = atomicAdd(flag_cnt, 1);
            flag_rows[sl] = gr;
        }
    }
}

// ---------------- batched exact fp32 rescore: 8 flagged rows per block ----------------
#define FB_ROWS 8
__global__ __launch_bounds__(256)
void vq_fallback_kernel(const float* __restrict__ ze, const float* __restrict__ emb,
                        const float* __restrict__ hn) {
    int base = blockIdx.x * FB_ROWS;
    int cnt = g_flagcnt[0];
    if (base >= cnt) return;
    __shared__ float zs[256][FB_ROWS];
    __shared__ int   rowids[FB_ROWS];
    __shared__ float rv[256];
    __shared__ int   rix[256];
    int tid = threadIdx.x;
    int nrows = min(FB_ROWS, cnt - base);
    if (tid < FB_ROWS)
        rowids[tid] = g_flagrows[base + ((tid < nrows) ? tid : 0)];
    __syncthreads();
    #pragma unroll
    for (int j = 0; j < FB_ROWS; j++) {
        int r = rowids[j];
        int b = r >> 6, t = r & 63;
        zs[tid][j] = ze[(long)b * (HD * TQ) + tid * TQ + t];
    }
    __syncthreads();

    float best[FB_ROWS]; int bidx[FB_ROWS];
    #pragma unroll
    for (int j = 0; j < FB_ROWS; j++) { best[j] = -3.4e38f; bidx[j] = 0; }

    for (int i = 0; i < KC / 256; i++) {
        int n = tid + 256 * i;
        const float4* e4 = (const float4*)(emb + (long)n * HD);
        float acc[FB_ROWS];
        #pragma unroll
        for (int j = 0; j < FB_ROWS; j++) acc[j] = 0.f;
        #pragma unroll 4
        for (int k4 = 0; k4 < 64; k4++) {
            float4 ev = e4[k4];
            #pragma unroll
            for (int j = 0; j < FB_ROWS; j++) {
                acc[j] = fmaf(ev.x, zs[4 * k4 + 0][j], acc[j]);
                acc[j] = fmaf(ev.y, zs[4 * k4 + 1][j], acc[j]);
                acc[j] = fmaf(ev.z, zs[4 * k4 + 2][j], acc[j]);
                acc[j] = fmaf(ev.w, zs[4 * k4 + 3][j], acc[j]);
            }
        }
        float h = hn[n];
        #pragma unroll
        for (int j = 0; j < FB_ROWS; j++) {
            float s = acc[j] - h;
            if (s > best[j]) { best[j] = s; bidx[j] = n; }
        }
    }

    for (int j = 0; j < FB_ROWS; j++) {
        rv[tid] = best[j]; rix[tid] = bidx[j];
        __syncthreads();
        for (int o = 128; o > 0; o >>= 1) {
            if (tid < o) {
                float v2 = rv[tid + o]; int i2 = rix[tid + o];
                if (v2 > rv[tid] || (v2 == rv[tid] && i2 < rix[tid])) { rv[tid] = v2; rix[tid] = i2; }
            }
            __syncthreads();
        }
        if (tid == 0 && j < nrows) {
            g_idx[rowids[j]] = rix[0];
            g_score[rowids[j]] = rv[0];
        }
        __syncthreads();
    }
}

// ---------------- losses from scores ----------------
__global__ void lossout_kernel(float* out) {
    __shared__ float red[1024];
    int tid = threadIdx.x;
    float s = 0.f;
    for (int m = tid; m < NB * TQ; m += 1024)
        s += g_zn[m] - 2.f * g_score[m];
    red[tid] = s;
    __syncthreads();
    for (int o = 512; o; o >>= 1) {
        if (tid < o) red[tid] += red[tid + o];
        __syncthreads();
    }
    if (tid == 0) {
        float l = red[0] * (1.f / 4194304.f);
        out[LOSS_OFF + 0] = l;
        out[LOSS_OFF + 1] = l;
    }
}

__global__ void idxout_kernel(float* out) {
    int m = blockIdx.x * 256 + threadIdx.x;
    out[IDX_OFF + m] = (float)g_idx[m];
}

// ---------------- launch ----------------
extern "C" void kernel_launch(void* const* d_in, const int* in_sizes, int n_in,
                              void* d_out, int out_size) {
    const float* x   = (const float*)d_in[0];
    const float* ew0 = (const float*)d_in[1];  const float* eb0b = (const float*)d_in[2];
    const float* ew1 = (const float*)d_in[3];  const float* eb1b = (const float*)d_in[4];
    const float* ew2 = (const float*)d_in[5];  const float* eb2b = (const float*)d_in[6];
    const float* pw  = (const float*)d_in[7];  const float* pb   = (const float*)d_in[8];
    const float* emb = (const float*)d_in[9];
    const float* dw0 = (const float*)d_in[10]; const float* db0 = (const float*)d_in[11];
    const float* dw1 = (const float*)d_in[12]; const float* db1 = (const float*)d_in[13];
    const float* dw2 = (const float*)d_in[14]; const float* db2 = (const float*)d_in[15];
    const float* dw3 = (const float*)d_in[16]; const float* db3 = (const float*)d_in[17];
    float* out = (float*)d_out;

    void* p;
    cudaGetSymbolAddress(&p, g_wt);   float* wt  = (float*)p;
    cudaGetSymbolAddress(&p, g_wtd);  float* wtd = (float*)p;
    cudaGetSymbolAddress(&p, g_eb0);  __nv_bfloat16* e0 = (__nv_bfloat16*)p;
    cudaGetSymbolAddress(&p, g_wc0h); __nv_bfloat16* wc0h = (__nv_bfloat16*)p;
    cudaGetSymbolAddress(&p, g_wc0l); __nv_bfloat16* wc0l = (__nv_bfloat16*)p;
    cudaGetSymbolAddress(&p, g_wc1h); __nv_bfloat16* wc1h = (__nv_bfloat16*)p;
    cudaGetSymbolAddress(&p, g_wc1l); __nv_bfloat16* wc1l = (__nv_bfloat16*)p;
    cudaGetSymbolAddress(&p, g_h0);   float* h0  = (float*)p;
    cudaGetSymbolAddress(&p, g_h1);   float* h1  = (float*)p;
    cudaGetSymbolAddress(&p, g_h2);   float* h2  = (float*)p;
    cudaGetSymbolAddress(&p, g_ze);   float* ze  = (float*)p;
    cudaGetSymbolAddress(&p, g_Y0);   float* Y0  = (float*)p;
    cudaGetSymbolAddress(&p, g_Y1);   float* Y1  = (float*)p;
    cudaGetSymbolAddress(&p, g_d2);   float* d2  = (float*)p;
    cudaGetSymbolAddress(&p, g_hn);   float* hn  = (float*)p;
    cudaGetSymbolAddress(&p, g_idx);  int*   ix  = (int*)p;
    cudaGetSymbolAddress(&p, g_score); float* sc = (float*)p;
    cudaGetSymbolAddress(&p, g_zn);   float* zn  = (float*)p;
    cudaGetSymbolAddress(&p, g_flagcnt);  int* fcnt = (int*)p;
    cudaGetSymbolAddress(&p, g_flagrows); int* frow = (int*)p;

    cudaFuncSetAttribute(vq_mma_kernel, cudaFuncAttributeMaxDynamicSharedMemorySize, VQT_SMEM);
    cudaFuncSetAttribute(gemm_dec_kernel<true, 12, 1>,  cudaFuncAttributeMaxDynamicSharedMemorySize, GD_SMEM);
    cudaFuncSetAttribute(gemm_dec_kernel<false, 6, 2>,  cudaFuncAttributeMaxDynamicSharedMemorySize, GD_SMEM);

    // prep: enc/proj transposes + dec2/dec3 dup + W_cat splits + codebook
    WtArgs wa;
    const float* srcs[6] = {ew0, ew1, ew2, pw, dw2, dw3};
    int offs[6]  = {WT0, WT1, WT2, WTP, WD2, WD3};
    int couts[6] = {64, 128, 256, 256, 64, 32};
    int cinks[6] = {32*3, 64*3, 128*3, 256, 128*3, 64*3};
    int acc = 0;
    for (int q = 0; q < 6; q++) {
        wa.src[q] = srcs[q]; wa.dst_off[q] = offs[q];
        wa.cout[q] = couts[q]; wa.cink[q] = cinks[q];
        wa.start[q] = acc; acc += couts[q] * cinks[q];
    }
    wa.total = acc;
    for (int q = 6; q < 8; q++) { wa.src[q] = nullptr; wa.dst_off[q] = 0; wa.cout[q] = 1; wa.cink[q] = 1; wa.start[q] = acc; }
    wtrans_all_kernel<<<(acc + 255) / 256, 256>>>(wa, wt, wtd);
    wcat_kernel<<<1152, 256>>>(dw0, dw1);
    ebnorm_kernel<<<KC/8, 256>>>(emb, e0);

    // encoder
    conv1d_kernel<32, 64, 32, 2, 1, true, true ><<<dim3(NB, 8), 64 >>>(x,  wt+WT0, eb0b, h0, 512, 256, 512*32, 1,  32);
    conv1d_kernel<64, 128,16, 2, 1, true, false><<<dim3(NB, 8), 128>>>(h0, wt+WT1, eb1b, h1, 256, 128, 64*256, 256, 1);
    conv1d_kernel<128,256,16, 2, 1, true, false><<<dim3(NB, 4), 256>>>(h1, wt+WT2, eb2b, h2, 128, 64,  128*128,128, 1);
    proj_kernel<<<dim3(NB, 4), 256>>>(h2, wt+WTP, pb, ze);

    // vector quantizer
    vq_mma_kernel<<<NB, 256, VQT_SMEM>>>(ze, e0, hn, ix, sc, zn, fcnt, frow);
    vq_fallback_kernel<<<16384 / FB_ROWS, 256>>>(ze, emb, hn);
    lossout_kernel<<<1, 1024>>>(out);
    idxout_kernel<<<64, 256>>>(out);

    // decoder: dec0/dec1 as bf16-split GEMMs, dec2 fused-Y1 FFMA2, dec3 FFMA2
    gemm_dec_kernel<true, 12, 1><<<256, 256, GD_SMEM>>>(ix, emb, nullptr, nullptr, wc0h, wc0l, Y0);
    gemm_dec_kernel<false, 6, 2><<<512, 256, GD_SMEM>>>(nullptr, nullptr, Y0, db0, wc1h, wc1l, Y1);
    deconv1d_kernel<128,64, 16,2, true, 2><<<dim3(NB,16), dim3(64, 2)>>>(nullptr, wtd+WD2, db2, d2, 256, 64*512,  512, 1, Y1, db1);
    deconv1d_kernel<64, 32, 16,4, false,0><<<dim3(NB,16), dim3(32, 4)>>>(d2, wtd+WD3, db3, out,512, 1024*32, 1,  32, nullptr, nullptr);
}